// round 1
// baseline (speedup 1.0000x reference)
#include <cuda_runtime.h>
#include <math.h>

// Problem constants
#define Bsz 4096
#define Jn  17
#define Cn  512
#define Kn  3
#define TOKn 256
#define CHn 2048
#define M2  (Bsz*Jn)       // 69632
#define KC  (Kn*Cn)        // 1536
#define EPSF 1e-5f

// ---------------- scratch (device globals; allocation-free rule) -------------
__device__ float g_xa  [M2 * KC];        // 428 MB  (xa1 then reused for xa2)
__device__ float g_x2  [Bsz*Jn*Cn];      // 143 MB  (stage-1 result, (B,J,C))
__device__ float g_xn2 [Bsz*Jn*Cn];      // 143 MB
__device__ float g_h   [M2 * CHn];       // 570 MB  (MLP2 hidden)
__device__ float g_Wr1 [KC * Cn];        // 3 MB
__device__ float g_Wr2 [KC * Cn];
__device__ float g_W21t[Cn * CHn];       // 4 MB
__device__ float g_W22t[CHn * Cn];
__device__ float g_b1m [Jn * Cn];        // gcn bias folded through adjacency
__device__ float g_b2m [Jn * Cn];

__device__ __forceinline__ float gelu_f(float v) {
    return 0.5f * v * (1.0f + erff(v * 0.7071067811865476f));
}

// ---------------- prep: weight transposes + gcn bias matrices ----------------
__global__ void prep_kernel(const float* __restrict__ Wg1, const float* __restrict__ Wg2,
                            const float* __restrict__ W21, const float* __restrict__ W22,
                            const float* __restrict__ bg1, const float* __restrict__ bg2,
                            const float* __restrict__ adj)
{
    int i = blockIdx.x * 256 + threadIdx.x;
    const int S1 = KC * Cn;          // 786432
    const int S3 = Cn * CHn;         // 1048576
    if (i < S1) {                    // Wr1[kc*512+o] = Wg1[k][o][c]
        int kc = i >> 9, o = i & 511;
        int k = kc >> 9, c = kc & 511;
        g_Wr1[i] = Wg1[k * (Cn*Cn) + o * Cn + c];
        return;
    }
    i -= S1;
    if (i < S1) {
        int kc = i >> 9, o = i & 511;
        int k = kc >> 9, c = kc & 511;
        g_Wr2[i] = Wg2[k * (Cn*Cn) + o * Cn + c];
        return;
    }
    i -= S1;
    if (i < S3) {                    // W21t[c*2048+ch] = W21[ch][c]
        int c = i >> 11, ch = i & 2047;
        g_W21t[i] = W21[ch * Cn + c];
        return;
    }
    i -= S3;
    if (i < S3) {                    // W22t[ch*512+c] = W22[c][ch]
        int ch = i >> 9, c = i & 511;
        g_W22t[i] = W22[c * CHn + ch];
        return;
    }
    i -= S3;
    if (i < Jn * Cn) {               // b1m[w*512+o] = sum_k bg1[k,o]*colsum_v(adj[k,:,w])
        int w = i >> 9, o = i & 511;
        float s = 0.f;
        #pragma unroll
        for (int k = 0; k < Kn; k++) {
            float cs = 0.f;
            #pragma unroll
            for (int v = 0; v < Jn; v++) cs += adj[k*289 + v*17 + w];
            s += bg1[k * Cn + o] * cs;
        }
        g_b1m[i] = s;
        return;
    }
    i -= Jn * Cn;
    if (i < Jn * Cn) {
        int w = i >> 9, o = i & 511;
        float s = 0.f;
        #pragma unroll
        for (int k = 0; k < Kn; k++) {
            float cs = 0.f;
            #pragma unroll
            for (int v = 0; v < Jn; v++) cs += adj[k*289 + v*17 + w];
            s += bg2[k * Cn + o] * cs;
        }
        g_b2m[i] = s;
        return;
    }
}

// ---------------- stage 1: LN(J) + xa1 + fused MLP1 + residual ---------------
// one block per b; each thread owns 2 channels: c and c+256
__global__ __launch_bounds__(256) void stage1_kernel(
    const float* __restrict__ x, const float* __restrict__ adj,
    const float* __restrict__ g1, const float* __restrict__ be1,
    const float* __restrict__ W11, const float* __restrict__ b11,
    const float* __restrict__ W12, const float* __restrict__ b12)
{
    __shared__ float sW11[TOKn * 18];      // [t][v], padded
    __shared__ float sW12[TOKn * 18];      // [t][j], padded
    __shared__ float sb11[TOKn];
    __shared__ float sadjT[Kn * Jn * 18];  // [k][w][v], padded
    __shared__ float sg1[Jn], sbe1[Jn], sb12[Jn];

    const int tid = threadIdx.x;
    const int b = blockIdx.x;

    for (int i = tid; i < TOKn * Jn; i += 256) { int t = i / 17, v = i % 17; sW11[t*18 + v] = W11[i]; }
    for (int i = tid; i < Jn * TOKn; i += 256) { int j = i >> 8, t = i & 255; sW12[t*18 + j] = W12[i]; }
    for (int i = tid; i < TOKn; i += 256) { sW11[i*18 + 17] = 0.f; sW12[i*18 + 17] = 0.f; sb11[i] = b11[i]; }
    for (int i = tid; i < Kn*Jn*Jn; i += 256) { int k = i/289, r = i%289, v = r/17, w = r%17; sadjT[(k*17+w)*18 + v] = adj[i]; }
    for (int i = tid; i < Kn*Jn; i += 256) sadjT[i*18 + 17] = 0.f;
    if (tid < Jn) { sg1[tid] = g1[tid]; sbe1[tid] = be1[tid]; sb12[tid] = b12[tid]; }
    __syncthreads();

    const int c0 = tid, c1 = tid + 256;
    const float* xb = x + (size_t)b * (Jn*Cn);

    float xr0[Jn], xr1[Jn];
    #pragma unroll
    for (int j = 0; j < Jn; j++) { xr0[j] = xb[j*Cn + c0]; xr1[j] = xb[j*Cn + c1]; }

    // LN over J
    float mu0 = 0.f, mu1 = 0.f;
    #pragma unroll
    for (int j = 0; j < Jn; j++) { mu0 += xr0[j]; mu1 += xr1[j]; }
    mu0 *= (1.0f/17.0f); mu1 *= (1.0f/17.0f);
    float v0 = 0.f, v1 = 0.f;
    #pragma unroll
    for (int j = 0; j < Jn; j++) { float d0 = xr0[j]-mu0, d1 = xr1[j]-mu1; v0 += d0*d0; v1 += d1*d1; }
    float rs0 = rsqrtf(v0*(1.0f/17.0f) + EPSF);
    float rs1 = rsqrtf(v1*(1.0f/17.0f) + EPSF);

    float xn0[18], xn1[18];
    #pragma unroll
    for (int j = 0; j < Jn; j++) {
        xn0[j] = (xr0[j]-mu0)*rs0*sg1[j] + sbe1[j];
        xn1[j] = (xr1[j]-mu1)*rs1*sg1[j] + sbe1[j];
    }
    xn0[17] = 0.f; xn1[17] = 0.f;

    // xa1[(b*17+w)*1536 + k*512 + c] = sum_v xn[v]*adj[k,v,w]
    #pragma unroll
    for (int k = 0; k < Kn; k++) {
        #pragma unroll
        for (int w = 0; w < Jn; w++) {
            const float2* ar = (const float2*)&sadjT[(k*17+w)*18];
            float s0 = 0.f, s1 = 0.f;
            #pragma unroll
            for (int p = 0; p < 9; p++) {
                float2 a = ar[p];
                s0 += a.x*xn0[2*p] + a.y*xn0[2*p+1];
                s1 += a.x*xn1[2*p] + a.y*xn1[2*p+1];
            }
            int idx = (b*17 + w)*KC + k*Cn;
            g_xa[idx + c0] = s0;
            g_xa[idx + c1] = s1;
        }
    }

    // fused MLP1: 17 -> 256 (gelu) -> 17
    float acc0[18], acc1[18];
    #pragma unroll
    for (int j = 0; j < Jn; j++) { acc0[j] = sb12[j]; acc1[j] = sb12[j]; }
    acc0[17] = 0.f; acc1[17] = 0.f;

    for (int t = 0; t < TOKn; t++) {
        const float2* wr = (const float2*)&sW11[t*18];
        float h0 = sb11[t], h1 = sb11[t];
        #pragma unroll
        for (int p = 0; p < 9; p++) {
            float2 w2 = wr[p];
            h0 += w2.x*xn0[2*p] + w2.y*xn0[2*p+1];
            h1 += w2.x*xn1[2*p] + w2.y*xn1[2*p+1];
        }
        h0 = gelu_f(h0); h1 = gelu_f(h1);
        const float2* wo = (const float2*)&sW12[t*18];
        #pragma unroll
        for (int p = 0; p < 9; p++) {
            float2 w2 = wo[p];
            acc0[2*p]   += w2.x*h0;  acc0[2*p+1] += w2.y*h0;
            acc1[2*p]   += w2.x*h1;  acc1[2*p+1] += w2.y*h1;
        }
    }

    // x2 partial = residual + mlp1 (g1_out added later by GEMM epilogue)
    float* x2b = g_x2 + (size_t)b * (Jn*Cn);
    #pragma unroll
    for (int j = 0; j < Jn; j++) {
        x2b[j*Cn + c0] = xr0[j] + acc0[j];
        x2b[j*Cn + c1] = xr1[j] + acc1[j];
    }
}

// ---------------- LN over C=512 (one warp per row) ---------------------------
__global__ __launch_bounds__(256) void ln2_kernel(const float* __restrict__ g2,
                                                  const float* __restrict__ be2)
{
    int row = blockIdx.x * 8 + (threadIdx.x >> 5);
    int lane = threadIdx.x & 31;
    const float4* xr = (const float4*)(g_x2 + (size_t)row * Cn);
    float4 a0 = xr[lane], a1 = xr[lane+32], a2 = xr[lane+64], a3 = xr[lane+96];
    float s = a0.x+a0.y+a0.z+a0.w + a1.x+a1.y+a1.z+a1.w
            + a2.x+a2.y+a2.z+a2.w + a3.x+a3.y+a3.z+a3.w;
    #pragma unroll
    for (int off = 16; off; off >>= 1) s += __shfl_xor_sync(0xffffffffu, s, off);
    float mu = s * (1.0f/512.0f);
    float q = 0.f;
    {
        float d;
        d=a0.x-mu; q+=d*d; d=a0.y-mu; q+=d*d; d=a0.z-mu; q+=d*d; d=a0.w-mu; q+=d*d;
        d=a1.x-mu; q+=d*d; d=a1.y-mu; q+=d*d; d=a1.z-mu; q+=d*d; d=a1.w-mu; q+=d*d;
        d=a2.x-mu; q+=d*d; d=a2.y-mu; q+=d*d; d=a2.z-mu; q+=d*d; d=a2.w-mu; q+=d*d;
        d=a3.x-mu; q+=d*d; d=a3.y-mu; q+=d*d; d=a3.z-mu; q+=d*d; d=a3.w-mu; q+=d*d;
    }
    #pragma unroll
    for (int off = 16; off; off >>= 1) q += __shfl_xor_sync(0xffffffffu, q, off);
    float rstd = rsqrtf(q * (1.0f/512.0f) + EPSF);

    const float4* gg = (const float4*)g2;
    const float4* bb = (const float4*)be2;
    float4* o = (float4*)(g_xn2 + (size_t)row * Cn);
    #pragma unroll
    for (int i = 0; i < 4; i++) {
        float4 a = (i==0)?a0:(i==1)?a1:(i==2)?a2:a3;
        float4 g = gg[lane + i*32], e = bb[lane + i*32];
        float4 r;
        r.x = (a.x-mu)*rstd*g.x + e.x;
        r.y = (a.y-mu)*rstd*g.y + e.y;
        r.z = (a.z-mu)*rstd*g.z + e.z;
        r.w = (a.w-mu)*rstd*g.w + e.w;
        o[lane + i*32] = r;
    }
}

// ---------------- xa2 from xn2 ----------------------------------------------
__global__ __launch_bounds__(256) void xa2_kernel(const float* __restrict__ adj)
{
    __shared__ float sadjT[Kn * Jn * 18];
    int tid = threadIdx.x;
    for (int i = tid; i < Kn*Jn*Jn; i += 256) { int k = i/289, r = i%289, v = r/17, w = r%17; sadjT[(k*17+w)*18 + v] = adj[i]; }
    for (int i = tid; i < Kn*Jn; i += 256) sadjT[i*18 + 17] = 0.f;
    __syncthreads();

    int gi = blockIdx.x * 256 + tid;
    int b = gi >> 9, c = gi & 511;
    float xv[18];
    #pragma unroll
    for (int v = 0; v < Jn; v++) xv[v] = g_xn2[(size_t)b*(Jn*Cn) + v*Cn + c];
    xv[17] = 0.f;
    #pragma unroll
    for (int k = 0; k < Kn; k++) {
        #pragma unroll
        for (int w = 0; w < Jn; w++) {
            const float2* ar = (const float2*)&sadjT[(k*17+w)*18];
            float s = 0.f;
            #pragma unroll
            for (int p = 0; p < 9; p++) { float2 a = ar[p]; s += a.x*xv[2*p] + a.y*xv[2*p+1]; }
            g_xa[(b*17 + w)*KC + k*Cn + c] = s;
        }
    }
}

// ---------------- generic 128x128x16 fp32 GEMM with epilogue variants --------
// EPI 0: out[r*512+c] += acc + b1m[(r%17)*512+c]                (accumulate into x2)
// EPI 1: out[r*2048+c] = gelu(acc + biasv[c])                   (MLP2 hidden)
// EPI 2: out[r*512+c] = aux[r*512+c] + acc + b2m[(r%17)*512+c]  (final base)
// EPI 3: out[r*512+c] += acc + biasv[c]                         (final add)
#define BMt 128
#define BNt 128
#define BKt 16

template<int EPI>
__global__ __launch_bounds__(256, 2) void gemm_k(
    const float* __restrict__ A, const float* __restrict__ Bm,
    float* __restrict__ out, const float* __restrict__ biasv,
    const float* __restrict__ aux, int Kd, int N)
{
    __shared__ float As[2][BKt][BMt + 4];
    __shared__ float Bs[2][BKt][BNt];

    const int tid = threadIdx.x;
    const int m0 = blockIdx.y * BMt;
    const int n0 = blockIdx.x * BNt;

    const int arow = tid >> 2;            // 0..63
    const int acol = (tid & 3) << 2;      // 0,4,8,12
    const int brow = tid >> 5;            // 0..7
    const int bcol = (tid & 31) << 2;

    const float* Aptr = A + (size_t)(m0 + arow) * Kd + acol;
    const float* Bptr = Bm + (size_t)brow * N + n0 + bcol;

    float4 aR0, aR1, bR0, bR1;
    aR0 = *(const float4*)(Aptr);
    aR1 = *(const float4*)(Aptr + (size_t)64 * Kd);
    bR0 = *(const float4*)(Bptr);
    bR1 = *(const float4*)(Bptr + (size_t)8 * N);

    {
        As[0][acol+0][arow] = aR0.x; As[0][acol+1][arow] = aR0.y;
        As[0][acol+2][arow] = aR0.z; As[0][acol+3][arow] = aR0.w;
        As[0][acol+0][arow+64] = aR1.x; As[0][acol+1][arow+64] = aR1.y;
        As[0][acol+2][arow+64] = aR1.z; As[0][acol+3][arow+64] = aR1.w;
        *(float4*)&Bs[0][brow][bcol] = bR0;
        *(float4*)&Bs[0][brow+8][bcol] = bR1;
    }
    __syncthreads();

    float acc[8][8];
    #pragma unroll
    for (int i = 0; i < 8; i++)
        #pragma unroll
        for (int j = 0; j < 8; j++) acc[i][j] = 0.f;

    const int ty = tid >> 4, tx = tid & 15;
    const int ao = ty * 8, bo = tx * 8;
    const int KT = Kd / BKt;

    for (int kt = 0; kt < KT; kt++) {
        int cur = kt & 1;
        if (kt + 1 < KT) {
            const float* Ap = Aptr + (kt + 1) * BKt;
            aR0 = *(const float4*)(Ap);
            aR1 = *(const float4*)(Ap + (size_t)64 * Kd);
            const float* Bp = Bptr + (size_t)(kt + 1) * BKt * N;
            bR0 = *(const float4*)(Bp);
            bR1 = *(const float4*)(Bp + (size_t)8 * N);
        }
        #pragma unroll
        for (int kk = 0; kk < BKt; kk++) {
            float ar[8], br[8];
            *(float4*)&ar[0] = *(const float4*)&As[cur][kk][ao];
            *(float4*)&ar[4] = *(const float4*)&As[cur][kk][ao + 4];
            *(float4*)&br[0] = *(const float4*)&Bs[cur][kk][bo];
            *(float4*)&br[4] = *(const float4*)&Bs[cur][kk][bo + 4];
            #pragma unroll
            for (int i = 0; i < 8; i++)
                #pragma unroll
                for (int j = 0; j < 8; j++)
                    acc[i][j] += ar[i] * br[j];
        }
        if (kt + 1 < KT) {
            int nxt = (kt + 1) & 1;
            As[nxt][acol+0][arow] = aR0.x; As[nxt][acol+1][arow] = aR0.y;
            As[nxt][acol+2][arow] = aR0.z; As[nxt][acol+3][arow] = aR0.w;
            As[nxt][acol+0][arow+64] = aR1.x; As[nxt][acol+1][arow+64] = aR1.y;
            As[nxt][acol+2][arow+64] = aR1.z; As[nxt][acol+3][arow+64] = aR1.w;
            *(float4*)&Bs[nxt][brow][bcol] = bR0;
            *(float4*)&Bs[nxt][brow+8][bcol] = bR1;
        }
        __syncthreads();
    }

    const int rbase = m0 + ao;
    const int cbase = n0 + bo;
    #pragma unroll
    for (int i = 0; i < 8; i++) {
        int r = rbase + i;
        if (EPI == 0) {
            float* p = out + (size_t)r * 512 + cbase;
            const float* bb = biasv + (r % 17) * 512 + cbase;
            float4 o0 = *(float4*)p, o1 = *(float4*)(p + 4);
            float4 b0 = *(const float4*)bb, b1 = *(const float4*)(bb + 4);
            o0.x += acc[i][0] + b0.x; o0.y += acc[i][1] + b0.y;
            o0.z += acc[i][2] + b0.z; o0.w += acc[i][3] + b0.w;
            o1.x += acc[i][4] + b1.x; o1.y += acc[i][5] + b1.y;
            o1.z += acc[i][6] + b1.z; o1.w += acc[i][7] + b1.w;
            *(float4*)p = o0; *(float4*)(p + 4) = o1;
        } else if (EPI == 1) {
            float* p = out + (size_t)r * 2048 + cbase;
            const float* bb = biasv + cbase;
            float4 o0, o1;
            o0.x = gelu_f(acc[i][0] + bb[0]); o0.y = gelu_f(acc[i][1] + bb[1]);
            o0.z = gelu_f(acc[i][2] + bb[2]); o0.w = gelu_f(acc[i][3] + bb[3]);
            o1.x = gelu_f(acc[i][4] + bb[4]); o1.y = gelu_f(acc[i][5] + bb[5]);
            o1.z = gelu_f(acc[i][6] + bb[6]); o1.w = gelu_f(acc[i][7] + bb[7]);
            *(float4*)p = o0; *(float4*)(p + 4) = o1;
        } else if (EPI == 2) {
            float* p = out + (size_t)r * 512 + cbase;
            const float* ax = aux + (size_t)r * 512 + cbase;
            const float* bb = biasv + (r % 17) * 512 + cbase;
            float4 a0 = *(const float4*)ax, a1 = *(const float4*)(ax + 4);
            float4 b0 = *(const float4*)bb, b1 = *(const float4*)(bb + 4);
            float4 o0, o1;
            o0.x = a0.x + acc[i][0] + b0.x; o0.y = a0.y + acc[i][1] + b0.y;
            o0.z = a0.z + acc[i][2] + b0.z; o0.w = a0.w + acc[i][3] + b0.w;
            o1.x = a1.x + acc[i][4] + b1.x; o1.y = a1.y + acc[i][5] + b1.y;
            o1.z = a1.z + acc[i][6] + b1.z; o1.w = a1.w + acc[i][7] + b1.w;
            *(float4*)p = o0; *(float4*)(p + 4) = o1;
        } else {
            float* p = out + (size_t)r * 512 + cbase;
            const float* bb = biasv + cbase;
            float4 o0 = *(float4*)p, o1 = *(float4*)(p + 4);
            o0.x += acc[i][0] + bb[0]; o0.y += acc[i][1] + bb[1];
            o0.z += acc[i][2] + bb[2]; o0.w += acc[i][3] + bb[3];
            o1.x += acc[i][4] + bb[4]; o1.y += acc[i][5] + bb[5];
            o1.z += acc[i][6] + bb[6]; o1.w += acc[i][7] + bb[7];
            *(float4*)p = o0; *(float4*)(p + 4) = o1;
        }
    }
}

// ---------------- launch ------------------------------------------------------
extern "C" void kernel_launch(void* const* d_in, const int* in_sizes, int n_in,
                              void* d_out, int out_size)
{
    const float* x   = (const float*)d_in[0];
    const float* adj = (const float*)d_in[1];
    const float* g1  = (const float*)d_in[2];
    const float* be1 = (const float*)d_in[3];
    const float* g2  = (const float*)d_in[4];
    const float* be2 = (const float*)d_in[5];
    const float* Wg1 = (const float*)d_in[6];
    const float* bg1 = (const float*)d_in[7];
    const float* Wg2 = (const float*)d_in[8];
    const float* bg2 = (const float*)d_in[9];
    const float* W11 = (const float*)d_in[10];
    const float* b11 = (const float*)d_in[11];
    const float* W12 = (const float*)d_in[12];
    const float* b12 = (const float*)d_in[13];
    const float* W21 = (const float*)d_in[14];
    const float* b21 = (const float*)d_in[15];
    const float* W22 = (const float*)d_in[16];
    const float* b22 = (const float*)d_in[17];
    float* out = (float*)d_out;

    float *p_xa, *p_x2, *p_xn2, *p_h, *p_Wr1, *p_Wr2, *p_W21t, *p_W22t, *p_b1m, *p_b2m;
    cudaGetSymbolAddress((void**)&p_xa,   g_xa);
    cudaGetSymbolAddress((void**)&p_x2,   g_x2);
    cudaGetSymbolAddress((void**)&p_xn2,  g_xn2);
    cudaGetSymbolAddress((void**)&p_h,    g_h);
    cudaGetSymbolAddress((void**)&p_Wr1,  g_Wr1);
    cudaGetSymbolAddress((void**)&p_Wr2,  g_Wr2);
    cudaGetSymbolAddress((void**)&p_W21t, g_W21t);
    cudaGetSymbolAddress((void**)&p_W22t, g_W22t);
    cudaGetSymbolAddress((void**)&p_b1m,  g_b1m);
    cudaGetSymbolAddress((void**)&p_b2m,  g_b2m);

    // 1) weight prep
    {
        int total = 2*(KC*Cn) + 2*(Cn*CHn) + 2*(Jn*Cn);
        prep_kernel<<<(total + 255)/256, 256>>>(Wg1, Wg2, W21, W22, bg1, bg2, adj);
    }
    // 2) stage1: LN(J) + xa1 + fused MLP1 + residual -> g_x2 partial
    stage1_kernel<<<Bsz, 256>>>(x, adj, g1, be1, W11, b11, W12, b12);
    // 3) GCN1 GEMM: g_x2 += xa1 @ Wr1 + b1m     (M=69632, K=1536, N=512)
    gemm_k<0><<<dim3(Cn/BNt, M2/BMt), 256>>>(p_xa, p_Wr1, p_x2, p_b1m, nullptr, KC, Cn);
    // 4) LN over C -> g_xn2
    ln2_kernel<<<M2/8, 256>>>(g2, be2);
    // 5) xa2 from xn2 (reuse g_xa)
    xa2_kernel<<<(Bsz*Cn)/256, 256>>>(adj);
    // 6) MLP2 up: g_h = gelu(xn2 @ W21t + b21)  (M=69632, K=512, N=2048)
    gemm_k<1><<<dim3(CHn/BNt, M2/BMt), 256>>>(p_xn2, p_W21t, p_h, b21, nullptr, Cn, CHn);
    // 7) GCN2 GEMM: out = x2 + xa2 @ Wr2 + b2m  (M=69632, K=1536, N=512)
    gemm_k<2><<<dim3(Cn/BNt, M2/BMt), 256>>>(p_xa, p_Wr2, out, p_b2m, p_x2, KC, Cn);
    // 8) MLP2 down: out += h @ W22t + b22       (M=69632, K=2048, N=512)
    gemm_k<3><<<dim3(Cn/BNt, M2/BMt), 256>>>(p_h, p_W22t, out, b22, nullptr, CHn, Cn);
}

// round 2
// speedup vs baseline: 2.0132x; 2.0132x over previous
#include <cuda_runtime.h>
#include <math.h>
#include <stdint.h>

// Problem constants
#define Bsz 4096
#define Jn  17
#define Cn  512
#define Kn  3
#define TOKn 256
#define CHn 2048
#define M2  (Bsz*Jn)       // 69632
#define KC  (Kn*Cn)        // 1536
#define EPSF 1e-5f

// ---------------- scratch (device globals; allocation-free rule) -------------
__device__ float g_xa  [M2 * KC];        // xa1 then reused for xa2 (tf32-rounded)
__device__ float g_x2  [Bsz*Jn*Cn];      // stage-1 result (B,J,C), fp32
__device__ float g_xn2 [Bsz*Jn*Cn];      // LN2 output, tf32-rounded
__device__ float g_h   [M2 * CHn];       // MLP2 hidden, tf32-rounded
__device__ float g_Wr1 [Cn * KC];        // [o][k*512+c], tf32-rounded
__device__ float g_Wr2 [Cn * KC];
__device__ float g_W21r[CHn * Cn];       // [ch][c], tf32-rounded
__device__ float g_W22r[Cn * CHn];       // [c][ch], tf32-rounded
__device__ float g_b1m [Jn * Cn];
__device__ float g_b2m [Jn * Cn];

__device__ __forceinline__ float gelu_f(float v) {
    return 0.5f * v * (1.0f + erff(v * 0.7071067811865476f));
}
__device__ __forceinline__ float rtf32(float x) {
    uint32_t u;
    asm("cvt.rna.tf32.f32 %0, %1;" : "=r"(u) : "f"(x));
    return __uint_as_float(u);
}

// ---------------- PTX wrappers ----------------------------------------------
__device__ __forceinline__ void mma_tf32(float* d, const uint32_t* a, const uint32_t* b) {
    asm volatile(
        "mma.sync.aligned.m16n8k8.row.col.f32.tf32.tf32.f32 "
        "{%0,%1,%2,%3}, {%4,%5,%6,%7}, {%8,%9}, {%0,%1,%2,%3};"
        : "+f"(d[0]), "+f"(d[1]), "+f"(d[2]), "+f"(d[3])
        : "r"(a[0]), "r"(a[1]), "r"(a[2]), "r"(a[3]), "r"(b[0]), "r"(b[1]));
}
__device__ __forceinline__ void ldsm4(uint32_t* r, uint32_t addr) {
    asm volatile("ldmatrix.sync.aligned.m8n8.x4.shared.b16 {%0,%1,%2,%3}, [%4];"
                 : "=r"(r[0]), "=r"(r[1]), "=r"(r[2]), "=r"(r[3]) : "r"(addr));
}
__device__ __forceinline__ void cpasync16(uint32_t smem, const void* g) {
    asm volatile("cp.async.cg.shared.global [%0], [%1], 16;" :: "r"(smem), "l"(g));
}
__device__ __forceinline__ void cp_commit() {
    asm volatile("cp.async.commit_group;" ::: "memory");
}
__device__ __forceinline__ void cp_wait1() {
    asm volatile("cp.async.wait_group 1;" ::: "memory");
}

// ---------------- prep: weight layouts + tf32 rounding + gcn bias ------------
__global__ void prep_kernel(const float* __restrict__ Wg1, const float* __restrict__ Wg2,
                            const float* __restrict__ W21, const float* __restrict__ W22,
                            const float* __restrict__ bg1, const float* __restrict__ bg2,
                            const float* __restrict__ adj)
{
    int i = blockIdx.x * 256 + threadIdx.x;
    const int S1 = Cn * KC;          // 786432
    const int S3 = Cn * CHn;         // 1048576
    if (i < S1) {                    // Wr1[o][k*512+c] = Wg1[k][o][c]
        int o = i / KC, rem = i % KC;
        int k = rem >> 9, c = rem & 511;
        g_Wr1[i] = rtf32(Wg1[k * (Cn*Cn) + o * Cn + c]);
        return;
    }
    i -= S1;
    if (i < S1) {
        int o = i / KC, rem = i % KC;
        int k = rem >> 9, c = rem & 511;
        g_Wr2[i] = rtf32(Wg2[k * (Cn*Cn) + o * Cn + c]);
        return;
    }
    i -= S1;
    if (i < S3) { g_W21r[i] = rtf32(W21[i]); return; }   // [ch][c] as-is
    i -= S3;
    if (i < S3) { g_W22r[i] = rtf32(W22[i]); return; }   // [c][ch] as-is
    i -= S3;
    if (i < Jn * Cn) {               // b1m[w*512+o]
        int w = i >> 9, o = i & 511;
        float s = 0.f;
        #pragma unroll
        for (int k = 0; k < Kn; k++) {
            float cs = 0.f;
            #pragma unroll
            for (int v = 0; v < Jn; v++) cs += adj[k*289 + v*17 + w];
            s += bg1[k * Cn + o] * cs;
        }
        g_b1m[i] = s;
        return;
    }
    i -= Jn * Cn;
    if (i < Jn * Cn) {
        int w = i >> 9, o = i & 511;
        float s = 0.f;
        #pragma unroll
        for (int k = 0; k < Kn; k++) {
            float cs = 0.f;
            #pragma unroll
            for (int v = 0; v < Jn; v++) cs += adj[k*289 + v*17 + w];
            s += bg2[k * Cn + o] * cs;
        }
        g_b2m[i] = s;
        return;
    }
}

// ---------------- stage 1: LN(J) + xa1 + fused MLP1 + residual ---------------
__global__ __launch_bounds__(256) void stage1_kernel(
    const float* __restrict__ x, const float* __restrict__ adj,
    const float* __restrict__ g1, const float* __restrict__ be1,
    const float* __restrict__ W11, const float* __restrict__ b11,
    const float* __restrict__ W12, const float* __restrict__ b12)
{
    __shared__ float sW11[TOKn * 18];
    __shared__ float sW12[TOKn * 18];
    __shared__ float sb11[TOKn];
    __shared__ float sadjT[Kn * Jn * 18];
    __shared__ float sg1[Jn], sbe1[Jn], sb12[Jn];

    const int tid = threadIdx.x;
    const int b = blockIdx.x;

    for (int i = tid; i < TOKn * Jn; i += 256) { int t = i / 17, v = i % 17; sW11[t*18 + v] = W11[i]; }
    for (int i = tid; i < Jn * TOKn; i += 256) { int j = i >> 8, t = i & 255; sW12[t*18 + j] = W12[i]; }
    for (int i = tid; i < TOKn; i += 256) { sW11[i*18 + 17] = 0.f; sW12[i*18 + 17] = 0.f; sb11[i] = b11[i]; }
    for (int i = tid; i < Kn*Jn*Jn; i += 256) { int k = i/289, r = i%289, v = r/17, w = r%17; sadjT[(k*17+w)*18 + v] = adj[i]; }
    for (int i = tid; i < Kn*Jn; i += 256) sadjT[i*18 + 17] = 0.f;
    if (tid < Jn) { sg1[tid] = g1[tid]; sbe1[tid] = be1[tid]; sb12[tid] = b12[tid]; }
    __syncthreads();

    const int c0 = tid, c1 = tid + 256;
    const float* xb = x + (size_t)b * (Jn*Cn);

    float xr0[Jn], xr1[Jn];
    #pragma unroll
    for (int j = 0; j < Jn; j++) { xr0[j] = xb[j*Cn + c0]; xr1[j] = xb[j*Cn + c1]; }

    float mu0 = 0.f, mu1 = 0.f;
    #pragma unroll
    for (int j = 0; j < Jn; j++) { mu0 += xr0[j]; mu1 += xr1[j]; }
    mu0 *= (1.0f/17.0f); mu1 *= (1.0f/17.0f);
    float v0 = 0.f, v1 = 0.f;
    #pragma unroll
    for (int j = 0; j < Jn; j++) { float d0 = xr0[j]-mu0, d1 = xr1[j]-mu1; v0 += d0*d0; v1 += d1*d1; }
    float rs0 = rsqrtf(v0*(1.0f/17.0f) + EPSF);
    float rs1 = rsqrtf(v1*(1.0f/17.0f) + EPSF);

    float xn0[18], xn1[18];
    #pragma unroll
    for (int j = 0; j < Jn; j++) {
        xn0[j] = (xr0[j]-mu0)*rs0*sg1[j] + sbe1[j];
        xn1[j] = (xr1[j]-mu1)*rs1*sg1[j] + sbe1[j];
    }
    xn0[17] = 0.f; xn1[17] = 0.f;

    // xa1 (tf32-rounded)
    #pragma unroll
    for (int k = 0; k < Kn; k++) {
        #pragma unroll
        for (int w = 0; w < Jn; w++) {
            const float2* ar = (const float2*)&sadjT[(k*17+w)*18];
            float s0 = 0.f, s1 = 0.f;
            #pragma unroll
            for (int p = 0; p < 9; p++) {
                float2 a = ar[p];
                s0 += a.x*xn0[2*p] + a.y*xn0[2*p+1];
                s1 += a.x*xn1[2*p] + a.y*xn1[2*p+1];
            }
            int idx = (b*17 + w)*KC + k*Cn;
            g_xa[idx + c0] = rtf32(s0);
            g_xa[idx + c1] = rtf32(s1);
        }
    }

    // fused MLP1: 17 -> 256 (gelu) -> 17
    float acc0[18], acc1[18];
    #pragma unroll
    for (int j = 0; j < Jn; j++) { acc0[j] = sb12[j]; acc1[j] = sb12[j]; }
    acc0[17] = 0.f; acc1[17] = 0.f;

    for (int t = 0; t < TOKn; t++) {
        const float2* wr = (const float2*)&sW11[t*18];
        float h0 = sb11[t], h1 = sb11[t];
        #pragma unroll
        for (int p = 0; p < 9; p++) {
            float2 w2 = wr[p];
            h0 += w2.x*xn0[2*p] + w2.y*xn0[2*p+1];
            h1 += w2.x*xn1[2*p] + w2.y*xn1[2*p+1];
        }
        h0 = gelu_f(h0); h1 = gelu_f(h1);
        const float2* wo = (const float2*)&sW12[t*18];
        #pragma unroll
        for (int p = 0; p < 9; p++) {
            float2 w2 = wo[p];
            acc0[2*p]   += w2.x*h0;  acc0[2*p+1] += w2.y*h0;
            acc1[2*p]   += w2.x*h1;  acc1[2*p+1] += w2.y*h1;
        }
    }

    float* x2b = g_x2 + (size_t)b * (Jn*Cn);
    #pragma unroll
    for (int j = 0; j < Jn; j++) {
        x2b[j*Cn + c0] = xr0[j] + acc0[j];
        x2b[j*Cn + c1] = xr1[j] + acc1[j];
    }
}

// ---------------- LN over C=512 (one warp per row), tf32-rounded out ---------
__global__ __launch_bounds__(256) void ln2_kernel(const float* __restrict__ g2,
                                                  const float* __restrict__ be2)
{
    int row = blockIdx.x * 8 + (threadIdx.x >> 5);
    int lane = threadIdx.x & 31;
    const float4* xr = (const float4*)(g_x2 + (size_t)row * Cn);
    float4 a0 = xr[lane], a1 = xr[lane+32], a2 = xr[lane+64], a3 = xr[lane+96];
    float s = a0.x+a0.y+a0.z+a0.w + a1.x+a1.y+a1.z+a1.w
            + a2.x+a2.y+a2.z+a2.w + a3.x+a3.y+a3.z+a3.w;
    #pragma unroll
    for (int off = 16; off; off >>= 1) s += __shfl_xor_sync(0xffffffffu, s, off);
    float mu = s * (1.0f/512.0f);
    float q = 0.f;
    {
        float d;
        d=a0.x-mu; q+=d*d; d=a0.y-mu; q+=d*d; d=a0.z-mu; q+=d*d; d=a0.w-mu; q+=d*d;
        d=a1.x-mu; q+=d*d; d=a1.y-mu; q+=d*d; d=a1.z-mu; q+=d*d; d=a1.w-mu; q+=d*d;
        d=a2.x-mu; q+=d*d; d=a2.y-mu; q+=d*d; d=a2.z-mu; q+=d*d; d=a2.w-mu; q+=d*d;
        d=a3.x-mu; q+=d*d; d=a3.y-mu; q+=d*d; d=a3.z-mu; q+=d*d; d=a3.w-mu; q+=d*d;
    }
    #pragma unroll
    for (int off = 16; off; off >>= 1) q += __shfl_xor_sync(0xffffffffu, q, off);
    float rstd = rsqrtf(q * (1.0f/512.0f) + EPSF);

    const float4* gg = (const float4*)g2;
    const float4* bb = (const float4*)be2;
    float4* o = (float4*)(g_xn2 + (size_t)row * Cn);
    #pragma unroll
    for (int i = 0; i < 4; i++) {
        float4 a = (i==0)?a0:(i==1)?a1:(i==2)?a2:a3;
        float4 g = gg[lane + i*32], e = bb[lane + i*32];
        float4 r;
        r.x = rtf32((a.x-mu)*rstd*g.x + e.x);
        r.y = rtf32((a.y-mu)*rstd*g.y + e.y);
        r.z = rtf32((a.z-mu)*rstd*g.z + e.z);
        r.w = rtf32((a.w-mu)*rstd*g.w + e.w);
        o[lane + i*32] = r;
    }
}

// ---------------- xa2 from xn2, tf32-rounded ---------------------------------
__global__ __launch_bounds__(256) void xa2_kernel(const float* __restrict__ adj)
{
    __shared__ float sadjT[Kn * Jn * 18];
    int tid = threadIdx.x;
    for (int i = tid; i < Kn*Jn*Jn; i += 256) { int k = i/289, r = i%289, v = r/17, w = r%17; sadjT[(k*17+w)*18 + v] = adj[i]; }
    for (int i = tid; i < Kn*Jn; i += 256) sadjT[i*18 + 17] = 0.f;
    __syncthreads();

    int gi = blockIdx.x * 256 + tid;
    int b = gi >> 9, c = gi & 511;
    float xv[18];
    #pragma unroll
    for (int v = 0; v < Jn; v++) xv[v] = g_xn2[(size_t)b*(Jn*Cn) + v*Cn + c];
    xv[17] = 0.f;
    #pragma unroll
    for (int k = 0; k < Kn; k++) {
        #pragma unroll
        for (int w = 0; w < Jn; w++) {
            const float2* ar = (const float2*)&sadjT[(k*17+w)*18];
            float s = 0.f;
            #pragma unroll
            for (int p = 0; p < 9; p++) { float2 a = ar[p]; s += a.x*xv[2*p] + a.y*xv[2*p+1]; }
            g_xa[(b*17 + w)*KC + k*Cn + c] = rtf32(s);
        }
    }
}

// ---------------- tf32 tensor-core GEMM, 128x128x32, 8 warps -----------------
// A: [M][Kd] row-major (tf32-rounded). Bw: [N][Kd] row-major (tf32-rounded).
// Computes acc = A @ Bw^T (i.e. out[m][n] = sum_k A[m][k]*Bw[n][k]).
// EPI 0: out[r*512+c] += acc + b1m[(r%17)*512+c]
// EPI 1: out[r*2048+c] = rtf32(gelu(acc + biasv[c]))
// EPI 2: out[r*512+c]  = aux[r*512+c] + acc + b2m[(r%17)*512+c]
// EPI 3: out[r*512+c] += acc + biasv[c]
#define SROW 36                      // 32 + 4 pad floats
#define STAGE_FLOATS (128*SROW)      // 4608
#define STAGE_BYTES  (STAGE_FLOATS*4)  // 18432
#define GEMM_SMEM    (4*STAGE_BYTES)   // 73728 (2 stages x {A,B})

template<int EPI>
__global__ __launch_bounds__(256, 2) void gemm_tc(
    const float* __restrict__ A, const float* __restrict__ Bw,
    float* __restrict__ out, const float* __restrict__ biasv,
    const float* __restrict__ aux, int Kd, int N)
{
    extern __shared__ float smem[];
    float* sA = smem;                      // [2][128][SROW]
    float* sB = smem + 2*STAGE_FLOATS;     // [2][128][SROW]

    const int tid = threadIdx.x;
    const int m0 = blockIdx.y * 128;
    const int n0 = blockIdx.x * 128;

    // cp.async source/dst: thread t loads 4 float4 of row (t>>1), cols (t&1)*16 + i*4
    const float* gA = A  + (size_t)(m0 + (tid >> 1)) * Kd + (tid & 1) * 16;
    const float* gB = Bw + (size_t)(n0 + (tid >> 1)) * Kd + (tid & 1) * 16;
    const uint32_t sA_w = (uint32_t)__cvta_generic_to_shared(sA + (tid >> 1)*SROW + (tid & 1)*16);
    const uint32_t sB_w = (uint32_t)__cvta_generic_to_shared(sB + (tid >> 1)*SROW + (tid & 1)*16);

    const int KT = Kd >> 5;

    // prologue: stage 0 and 1
    #pragma unroll
    for (int s = 0; s < 2; s++) {
        const float* ga = gA + s*32;
        const float* gb = gB + s*32;
        uint32_t da = sA_w + s*STAGE_BYTES;
        uint32_t db = sB_w + s*STAGE_BYTES;
        #pragma unroll
        for (int i = 0; i < 4; i++) {
            cpasync16(da + i*16, ga + i*4);
            cpasync16(db + i*16, gb + i*4);
        }
        cp_commit();
    }

    // ldmatrix per-thread base addresses
    const int lane = tid & 31, warp = tid >> 5;
    const int wm = warp >> 2, wn = warp & 3;    // warp tile: 64(M) x 32(N)
    const int quad = lane >> 3, qr = lane & 7;
    const int a_m = wm*64 + (quad & 1)*8 + qr;
    const int a_k = (quad >> 1) * 4;
    const uint32_t aAddr = (uint32_t)__cvta_generic_to_shared(sA + a_m*SROW + a_k);
    const int b_n = wn*32 + (quad >> 1)*8 + qr;
    const int b_k = (quad & 1) * 4;
    const uint32_t bAddr = (uint32_t)__cvta_generic_to_shared(sB + b_n*SROW + b_k);

    float acc[4][4][4];
    #pragma unroll
    for (int mi = 0; mi < 4; mi++)
        #pragma unroll
        for (int ni = 0; ni < 4; ni++)
            #pragma unroll
            for (int e = 0; e < 4; e++) acc[mi][ni][e] = 0.f;

    for (int kt = 0; kt < KT; kt++) {
        const int buf = kt & 1;
        cp_wait1();
        __syncthreads();
        const uint32_t aBase = aAddr + buf*STAGE_BYTES;
        const uint32_t bBase = bAddr + buf*STAGE_BYTES;
        #pragma unroll
        for (int ks = 0; ks < 4; ks++) {
            uint32_t af[4][4], bf[2][4];
            #pragma unroll
            for (int mi = 0; mi < 4; mi++)
                ldsm4(af[mi], aBase + (uint32_t)((mi*16*SROW + ks*8) * 4));
            #pragma unroll
            for (int nb = 0; nb < 2; nb++)
                ldsm4(bf[nb], bBase + (uint32_t)((nb*16*SROW + ks*8) * 4));
            #pragma unroll
            for (int mi = 0; mi < 4; mi++)
                #pragma unroll
                for (int ni = 0; ni < 4; ni++)
                    mma_tf32(acc[mi][ni], af[mi], &bf[ni >> 1][(ni & 1) * 2]);
        }
        __syncthreads();
        if (kt + 2 < KT) {
            const float* ga = gA + (kt + 2)*32;
            const float* gb = gB + (kt + 2)*32;
            uint32_t da = sA_w + buf*STAGE_BYTES;
            uint32_t db = sB_w + buf*STAGE_BYTES;
            #pragma unroll
            for (int i = 0; i < 4; i++) {
                cpasync16(da + i*16, ga + i*4);
                cpasync16(db + i*16, gb + i*4);
            }
            cp_commit();
        }
    }

    // epilogue
    const int g = lane >> 2, tg = lane & 3;
    #pragma unroll
    for (int mi = 0; mi < 4; mi++) {
        const int rb = m0 + wm*64 + mi*16 + g;
        #pragma unroll
        for (int half = 0; half < 2; half++) {
            const int r = rb + half*8;
            #pragma unroll
            for (int ni = 0; ni < 4; ni++) {
                const int c = n0 + wn*32 + ni*8 + tg*2;
                const float v0 = acc[mi][ni][half*2 + 0];
                const float v1 = acc[mi][ni][half*2 + 1];
                if (EPI == 0) {
                    float* p = out + (size_t)r * 512 + c;
                    const float* bb = biasv + (r % 17) * 512 + c;
                    float2 o = *(float2*)p;
                    o.x += v0 + bb[0]; o.y += v1 + bb[1];
                    *(float2*)p = o;
                } else if (EPI == 1) {
                    float* p = out + (size_t)r * 2048 + c;
                    const float* bb = biasv + c;
                    float2 o;
                    o.x = rtf32(gelu_f(v0 + bb[0]));
                    o.y = rtf32(gelu_f(v1 + bb[1]));
                    *(float2*)p = o;
                } else if (EPI == 2) {
                    float* p = out + (size_t)r * 512 + c;
                    const float* ax = aux + (size_t)r * 512 + c;
                    const float* bb = biasv + (r % 17) * 512 + c;
                    float2 a = *(const float2*)ax;
                    float2 o;
                    o.x = a.x + v0 + bb[0]; o.y = a.y + v1 + bb[1];
                    *(float2*)p = o;
                } else {
                    float* p = out + (size_t)r * 512 + c;
                    const float* bb = biasv + c;
                    float2 o = *(float2*)p;
                    o.x += v0 + bb[0]; o.y += v1 + bb[1];
                    *(float2*)p = o;
                }
            }
        }
    }
}

// ---------------- launch ------------------------------------------------------
extern "C" void kernel_launch(void* const* d_in, const int* in_sizes, int n_in,
                              void* d_out, int out_size)
{
    const float* x   = (const float*)d_in[0];
    const float* adj = (const float*)d_in[1];
    const float* g1  = (const float*)d_in[2];
    const float* be1 = (const float*)d_in[3];
    const float* g2  = (const float*)d_in[4];
    const float* be2 = (const float*)d_in[5];
    const float* Wg1 = (const float*)d_in[6];
    const float* bg1 = (const float*)d_in[7];
    const float* Wg2 = (const float*)d_in[8];
    const float* bg2 = (const float*)d_in[9];
    const float* W11 = (const float*)d_in[10];
    const float* b11 = (const float*)d_in[11];
    const float* W12 = (const float*)d_in[12];
    const float* b12 = (const float*)d_in[13];
    const float* W21 = (const float*)d_in[14];
    const float* b21 = (const float*)d_in[15];
    const float* W22 = (const float*)d_in[16];
    const float* b22 = (const float*)d_in[17];
    float* out = (float*)d_out;

    float *p_xa, *p_x2, *p_xn2, *p_h, *p_Wr1, *p_Wr2, *p_W21r, *p_W22r, *p_b1m, *p_b2m;
    cudaGetSymbolAddress((void**)&p_xa,   g_xa);
    cudaGetSymbolAddress((void**)&p_x2,   g_x2);
    cudaGetSymbolAddress((void**)&p_xn2,  g_xn2);
    cudaGetSymbolAddress((void**)&p_h,    g_h);
    cudaGetSymbolAddress((void**)&p_Wr1,  g_Wr1);
    cudaGetSymbolAddress((void**)&p_Wr2,  g_Wr2);
    cudaGetSymbolAddress((void**)&p_W21r, g_W21r);
    cudaGetSymbolAddress((void**)&p_W22r, g_W22r);
    cudaGetSymbolAddress((void**)&p_b1m,  g_b1m);
    cudaGetSymbolAddress((void**)&p_b2m,  g_b2m);

    static bool attr_done = false;
    if (!attr_done) {
        cudaFuncSetAttribute(gemm_tc<0>, cudaFuncAttributeMaxDynamicSharedMemorySize, GEMM_SMEM);
        cudaFuncSetAttribute(gemm_tc<1>, cudaFuncAttributeMaxDynamicSharedMemorySize, GEMM_SMEM);
        cudaFuncSetAttribute(gemm_tc<2>, cudaFuncAttributeMaxDynamicSharedMemorySize, GEMM_SMEM);
        cudaFuncSetAttribute(gemm_tc<3>, cudaFuncAttributeMaxDynamicSharedMemorySize, GEMM_SMEM);
        attr_done = true;
    }

    // 1) weight prep (layouts + tf32 rounding + gcn bias)
    {
        int total = 2*(Cn*KC) + 2*(Cn*CHn) + 2*(Jn*Cn);
        prep_kernel<<<(total + 255)/256, 256>>>(Wg1, Wg2, W21, W22, bg1, bg2, adj);
    }
    // 2) stage1: LN(J) + xa1 + fused MLP1 + residual -> g_x2 partial
    stage1_kernel<<<Bsz, 256>>>(x, adj, g1, be1, W11, b11, W12, b12);
    // 3) GCN1: g_x2 += xa1 @ Wr1^T + b1m        (M=69632, K=1536, N=512)
    gemm_tc<0><<<dim3(Cn/128, M2/128), 256, GEMM_SMEM>>>(p_xa, p_Wr1, p_x2, p_b1m, nullptr, KC, Cn);
    // 4) LN over C -> g_xn2 (tf32)
    ln2_kernel<<<M2/8, 256>>>(g2, be2);
    // 5) xa2 from xn2 (reuse g_xa, tf32)
    xa2_kernel<<<(Bsz*Cn)/256, 256>>>(adj);
    // 6) MLP2 up: g_h = rtf32(gelu(xn2 @ W21r^T + b21))  (M=69632, K=512, N=2048)
    gemm_tc<1><<<dim3(CHn/128, M2/128), 256, GEMM_SMEM>>>(p_xn2, p_W21r, p_h, b21, nullptr, Cn, CHn);
    // 7) GCN2: out = x2 + xa2 @ Wr2^T + b2m     (M=69632, K=1536, N=512)
    gemm_tc<2><<<dim3(Cn/128, M2/128), 256, GEMM_SMEM>>>(p_xa, p_Wr2, out, p_b2m, p_x2, KC, Cn);
    // 8) MLP2 down: out += h @ W22r^T + b22     (M=69632, K=2048, N=512)
    gemm_tc<3><<<dim3(Cn/128, M2/128), 256, GEMM_SMEM>>>(p_h, p_W22r, out, b22, nullptr, CHn, Cn);
}

// round 4
// speedup vs baseline: 3.1692x; 1.5742x over previous
#include <cuda_runtime.h>
#include <cuda_fp16.h>
#include <math.h>
#include <stdint.h>

// Problem constants
#define Bsz 4096
#define Jn  17
#define Cn  512
#define Kn  3
#define TOKn 256
#define CHn 2048
#define M2  (Bsz*Jn)       // 69632
#define KC  (Kn*Cn)        // 1536
#define EPSF 1e-5f

// ---------------- scratch (device globals; allocation-free rule) -------------
__device__ __half g_xah [M2 * KC];       // xa1 then xa2, fp16      (214 MB)
__device__ float  g_x2  [Bsz*Jn*Cn];     // stage-1 result, fp32    (143 MB)
__device__ __half g_xn2h[Bsz*Jn*Cn];     // LN2 output, fp16        (71 MB)
__device__ __half g_hh  [M2 * CHn];      // MLP2 hidden, fp16       (285 MB)
__device__ __half g_Wr1h[Cn * KC];       // [o][k*512+c]
__device__ __half g_Wr2h[Cn * KC];
__device__ __half g_W21h[CHn * Cn];      // [ch][c]
__device__ __half g_W22h[Cn * CHn];      // [c][ch]
__device__ float  g_b1m [Jn * Cn];
__device__ float  g_b2m [Jn * Cn];

__device__ __forceinline__ float gelu_f(float v) {
    return 0.5f * v * (1.0f + erff(v * 0.7071067811865476f));
}

// ---------------- PTX helpers ------------------------------------------------
__device__ __forceinline__ void mma_f16(float* d, const uint32_t* a, const uint32_t* b) {
    asm volatile(
        "mma.sync.aligned.m16n8k16.row.col.f32.f16.f16.f32 "
        "{%0,%1,%2,%3}, {%4,%5,%6,%7}, {%8,%9}, {%0,%1,%2,%3};"
        : "+f"(d[0]), "+f"(d[1]), "+f"(d[2]), "+f"(d[3])
        : "r"(a[0]), "r"(a[1]), "r"(a[2]), "r"(a[3]), "r"(b[0]), "r"(b[1]));
}
__device__ __forceinline__ void ldsm4(uint32_t* r, uint32_t addr) {
    asm volatile("ldmatrix.sync.aligned.m8n8.x4.shared.b16 {%0,%1,%2,%3}, [%4];"
                 : "=r"(r[0]), "=r"(r[1]), "=r"(r[2]), "=r"(r[3]) : "r"(addr));
}
__device__ __forceinline__ void cpasync16(uint32_t smem, const void* g) {
    asm volatile("cp.async.cg.shared.global [%0], [%1], 16;" :: "r"(smem), "l"(g));
}
__device__ __forceinline__ void cp_commit() {
    asm volatile("cp.async.commit_group;" ::: "memory");
}
template<int N_> __device__ __forceinline__ void cp_wait() {
    asm volatile("cp.async.wait_group %0;" :: "n"(N_) : "memory");
}

// ---------------- prep: weight layouts (fp16) + gcn bias ---------------------
__global__ void prep_kernel(const float* __restrict__ Wg1, const float* __restrict__ Wg2,
                            const float* __restrict__ W21, const float* __restrict__ W22,
                            const float* __restrict__ bg1, const float* __restrict__ bg2,
                            const float* __restrict__ adj)
{
    int i = blockIdx.x * 256 + threadIdx.x;
    const int S1 = Cn * KC;
    const int S3 = Cn * CHn;
    if (i < S1) {                    // Wr1[o][k*512+c] = Wg1[k][o][c]
        int o = i / KC, rem = i % KC;
        int k = rem >> 9, c = rem & 511;
        g_Wr1h[i] = __float2half_rn(Wg1[k * (Cn*Cn) + o * Cn + c]);
        return;
    }
    i -= S1;
    if (i < S1) {
        int o = i / KC, rem = i % KC;
        int k = rem >> 9, c = rem & 511;
        g_Wr2h[i] = __float2half_rn(Wg2[k * (Cn*Cn) + o * Cn + c]);
        return;
    }
    i -= S1;
    if (i < S3) { g_W21h[i] = __float2half_rn(W21[i]); return; }   // [ch][c]
    i -= S3;
    if (i < S3) { g_W22h[i] = __float2half_rn(W22[i]); return; }   // [c][ch]
    i -= S3;
    if (i < Jn * Cn) {
        int w = i >> 9, o = i & 511;
        float s = 0.f;
        #pragma unroll
        for (int k = 0; k < Kn; k++) {
            float cs = 0.f;
            #pragma unroll
            for (int v = 0; v < Jn; v++) cs += adj[k*289 + v*17 + w];
            s += bg1[k * Cn + o] * cs;
        }
        g_b1m[i] = s;
        return;
    }
    i -= Jn * Cn;
    if (i < Jn * Cn) {
        int w = i >> 9, o = i & 511;
        float s = 0.f;
        #pragma unroll
        for (int k = 0; k < Kn; k++) {
            float cs = 0.f;
            #pragma unroll
            for (int v = 0; v < Jn; v++) cs += adj[k*289 + v*17 + w];
            s += bg2[k * Cn + o] * cs;
        }
        g_b2m[i] = s;
        return;
    }
}

// ---------------- stage 1: LN(J) + xa1(fp16) + fused MLP1 + residual ---------
__global__ __launch_bounds__(256) void stage1_kernel(
    const float* __restrict__ x, const float* __restrict__ adj,
    const float* __restrict__ g1, const float* __restrict__ be1,
    const float* __restrict__ W11, const float* __restrict__ b11,
    const float* __restrict__ W12, const float* __restrict__ b12)
{
    __shared__ float sW11[TOKn * 18];
    __shared__ float sW12[TOKn * 18];
    __shared__ float sb11[TOKn];
    __shared__ float sadjT[Kn * Jn * 18];
    __shared__ float sg1[Jn], sbe1[Jn], sb12[Jn];

    const int tid = threadIdx.x;
    const int b = blockIdx.x;

    for (int i = tid; i < TOKn * Jn; i += 256) { int t = i / 17, v = i % 17; sW11[t*18 + v] = W11[i]; }
    for (int i = tid; i < Jn * TOKn; i += 256) { int j = i >> 8, t = i & 255; sW12[t*18 + j] = W12[i]; }
    for (int i = tid; i < TOKn; i += 256) { sW11[i*18 + 17] = 0.f; sW12[i*18 + 17] = 0.f; sb11[i] = b11[i]; }
    for (int i = tid; i < Kn*Jn*Jn; i += 256) { int k = i/289, r = i%289, v = r/17, w = r%17; sadjT[(k*17+w)*18 + v] = adj[i]; }
    for (int i = tid; i < Kn*Jn; i += 256) sadjT[i*18 + 17] = 0.f;
    if (tid < Jn) { sg1[tid] = g1[tid]; sbe1[tid] = be1[tid]; sb12[tid] = b12[tid]; }
    __syncthreads();

    const int c0 = tid, c1 = tid + 256;
    const float* xb = x + (size_t)b * (Jn*Cn);

    float xr0[Jn], xr1[Jn];
    #pragma unroll
    for (int j = 0; j < Jn; j++) { xr0[j] = xb[j*Cn + c0]; xr1[j] = xb[j*Cn + c1]; }

    float mu0 = 0.f, mu1 = 0.f;
    #pragma unroll
    for (int j = 0; j < Jn; j++) { mu0 += xr0[j]; mu1 += xr1[j]; }
    mu0 *= (1.0f/17.0f); mu1 *= (1.0f/17.0f);
    float v0 = 0.f, v1 = 0.f;
    #pragma unroll
    for (int j = 0; j < Jn; j++) { float d0 = xr0[j]-mu0, d1 = xr1[j]-mu1; v0 += d0*d0; v1 += d1*d1; }
    float rs0 = rsqrtf(v0*(1.0f/17.0f) + EPSF);
    float rs1 = rsqrtf(v1*(1.0f/17.0f) + EPSF);

    float xn0[18], xn1[18];
    #pragma unroll
    for (int j = 0; j < Jn; j++) {
        xn0[j] = (xr0[j]-mu0)*rs0*sg1[j] + sbe1[j];
        xn1[j] = (xr1[j]-mu1)*rs1*sg1[j] + sbe1[j];
    }
    xn0[17] = 0.f; xn1[17] = 0.f;

    #pragma unroll
    for (int k = 0; k < Kn; k++) {
        #pragma unroll
        for (int w = 0; w < Jn; w++) {
            const float2* ar = (const float2*)&sadjT[(k*17+w)*18];
            float s0 = 0.f, s1 = 0.f;
            #pragma unroll
            for (int p = 0; p < 9; p++) {
                float2 a = ar[p];
                s0 += a.x*xn0[2*p] + a.y*xn0[2*p+1];
                s1 += a.x*xn1[2*p] + a.y*xn1[2*p+1];
            }
            int idx = (b*17 + w)*KC + k*Cn;
            g_xah[idx + c0] = __float2half_rn(s0);
            g_xah[idx + c1] = __float2half_rn(s1);
        }
    }

    float acc0[18], acc1[18];
    #pragma unroll
    for (int j = 0; j < Jn; j++) { acc0[j] = sb12[j]; acc1[j] = sb12[j]; }
    acc0[17] = 0.f; acc1[17] = 0.f;

    for (int t = 0; t < TOKn; t++) {
        const float2* wr = (const float2*)&sW11[t*18];
        float h0 = sb11[t], h1 = sb11[t];
        #pragma unroll
        for (int p = 0; p < 9; p++) {
            float2 w2 = wr[p];
            h0 += w2.x*xn0[2*p] + w2.y*xn0[2*p+1];
            h1 += w2.x*xn1[2*p] + w2.y*xn1[2*p+1];
        }
        h0 = gelu_f(h0); h1 = gelu_f(h1);
        const float2* wo = (const float2*)&sW12[t*18];
        #pragma unroll
        for (int p = 0; p < 9; p++) {
            float2 w2 = wo[p];
            acc0[2*p]   += w2.x*h0;  acc0[2*p+1] += w2.y*h0;
            acc1[2*p]   += w2.x*h1;  acc1[2*p+1] += w2.y*h1;
        }
    }

    float* x2b = g_x2 + (size_t)b * (Jn*Cn);
    #pragma unroll
    for (int j = 0; j < Jn; j++) {
        x2b[j*Cn + c0] = xr0[j] + acc0[j];
        x2b[j*Cn + c1] = xr1[j] + acc1[j];
    }
}

// ---------------- LN over C=512 (one warp per row), fp16 out -----------------
__global__ __launch_bounds__(256) void ln2_kernel(const float* __restrict__ g2,
                                                  const float* __restrict__ be2)
{
    int row = blockIdx.x * 8 + (threadIdx.x >> 5);
    int lane = threadIdx.x & 31;
    const float4* xr = (const float4*)(g_x2 + (size_t)row * Cn);
    float4 a0 = xr[lane], a1 = xr[lane+32], a2 = xr[lane+64], a3 = xr[lane+96];
    float s = a0.x+a0.y+a0.z+a0.w + a1.x+a1.y+a1.z+a1.w
            + a2.x+a2.y+a2.z+a2.w + a3.x+a3.y+a3.z+a3.w;
    #pragma unroll
    for (int off = 16; off; off >>= 1) s += __shfl_xor_sync(0xffffffffu, s, off);
    float mu = s * (1.0f/512.0f);
    float q = 0.f;
    {
        float d;
        d=a0.x-mu; q+=d*d; d=a0.y-mu; q+=d*d; d=a0.z-mu; q+=d*d; d=a0.w-mu; q+=d*d;
        d=a1.x-mu; q+=d*d; d=a1.y-mu; q+=d*d; d=a1.z-mu; q+=d*d; d=a1.w-mu; q+=d*d;
        d=a2.x-mu; q+=d*d; d=a2.y-mu; q+=d*d; d=a2.z-mu; q+=d*d; d=a2.w-mu; q+=d*d;
        d=a3.x-mu; q+=d*d; d=a3.y-mu; q+=d*d; d=a3.z-mu; q+=d*d; d=a3.w-mu; q+=d*d;
    }
    #pragma unroll
    for (int off = 16; off; off >>= 1) q += __shfl_xor_sync(0xffffffffu, q, off);
    float rstd = rsqrtf(q * (1.0f/512.0f) + EPSF);

    const float4* gg = (const float4*)g2;
    const float4* bb = (const float4*)be2;
    __half2* oh = (__half2*)(g_xn2h + (size_t)row * Cn);
    #pragma unroll
    for (int i = 0; i < 4; i++) {
        float4 a = (i==0)?a0:(i==1)?a1:(i==2)?a2:a3;
        float4 g = gg[lane + i*32], e = bb[lane + i*32];
        int p = (lane + i*32) * 2;
        oh[p]   = __floats2half2_rn((a.x-mu)*rstd*g.x + e.x, (a.y-mu)*rstd*g.y + e.y);
        oh[p+1] = __floats2half2_rn((a.z-mu)*rstd*g.z + e.z, (a.w-mu)*rstd*g.w + e.w);
    }
}

// ---------------- xa2 from xn2 (fp16 in/out) ---------------------------------
__global__ __launch_bounds__(256) void xa2_kernel(const float* __restrict__ adj)
{
    __shared__ float sadjT[Kn * Jn * 18];
    int tid = threadIdx.x;
    for (int i = tid; i < Kn*Jn*Jn; i += 256) { int k = i/289, r = i%289, v = r/17, w = r%17; sadjT[(k*17+w)*18 + v] = adj[i]; }
    for (int i = tid; i < Kn*Jn; i += 256) sadjT[i*18 + 17] = 0.f;
    __syncthreads();

    int gi = blockIdx.x * 256 + tid;
    int b = gi >> 9, c = gi & 511;
    float xv[18];
    #pragma unroll
    for (int v = 0; v < Jn; v++) xv[v] = __half2float(g_xn2h[(size_t)b*(Jn*Cn) + v*Cn + c]);
    xv[17] = 0.f;
    #pragma unroll
    for (int k = 0; k < Kn; k++) {
        #pragma unroll
        for (int w = 0; w < Jn; w++) {
            const float2* ar = (const float2*)&sadjT[(k*17+w)*18];
            float s = 0.f;
            #pragma unroll
            for (int p = 0; p < 9; p++) { float2 a = ar[p]; s += a.x*xv[2*p] + a.y*xv[2*p+1]; }
            g_xah[(b*17 + w)*KC + k*Cn + c] = __float2half_rn(s);
        }
    }
}

// ---------------- fp16 tensor-core GEMM, 128x128x32, 4-stage cp.async --------
// A: [M][Kd] half row-major. Bw: [N][Kd] half row-major. acc = A @ Bw^T (fp32).
// smem rows: 64 B (32 halves), XOR swizzle: group' = group ^ ((row&6)>>1).
// EPI 0: x2 += acc + b1m[(r%17)*512+c]               (float out, stride 512)
// EPI 1: h = half(gelu(acc + biasv[c]))              (half out, stride 2048)
// EPI 2: out = aux + acc + b2m[(r%17)*512+c]         (float out, stride 512)
// EPI 3: out += acc + biasv[c]                       (float out, stride 512)
#define NSTAGE 4
#define ABYTES 8192                      // 128 rows x 64 B
#define STAGE_BYTES (2*ABYTES)           // 16384
#define GEMM_SMEM (NSTAGE*STAGE_BYTES)   // 65536

template<int EPI>
__global__ __launch_bounds__(256, 2) void gemm_f16(
    const __half* __restrict__ A, const __half* __restrict__ Bw,
    void* __restrict__ outp, const float* __restrict__ biasv,
    const float* __restrict__ aux, int Kd)
{
    extern __shared__ __align__(128) char smem[];
    uint32_t sbase;
    asm("{ .reg .u64 t; cvta.to.shared.u64 t, %1; cvt.u32.u64 %0, t; }" : "=r"(sbase) : "l"(smem));

    const int tid  = threadIdx.x;
    const int warp = tid >> 5;
    const int lane = tid & 31;
    const int m0 = blockIdx.y * 128;
    const int n0 = blockIdx.x * 128;
    const int KT = Kd >> 5;

    // -- load mapping: thread t -> row t>>1, two 16B groups (gsel selects pair)
    const int lrow = tid >> 1;
    const int gsel = tid & 1;
    const int xw   = (lrow & 6) >> 1;
    const __half* gA = A  + (size_t)(m0 + lrow) * Kd + gsel * 16;
    const __half* gB = Bw + (size_t)(n0 + lrow) * Kd + gsel * 16;
    const uint32_t dA0 = sbase + lrow*64 + (((gsel*2 + 0) ^ xw) << 4);
    const uint32_t dA1 = sbase + lrow*64 + (((gsel*2 + 1) ^ xw) << 4);
    const uint32_t dB0 = dA0 + ABYTES;
    const uint32_t dB1 = dA1 + ABYTES;

    // prologue: stages 0..2
    #pragma unroll
    for (int s = 0; s < NSTAGE - 1; s++) {
        const uint32_t so = s * STAGE_BYTES;
        cpasync16(dA0 + so, gA + s*32);
        cpasync16(dA1 + so, gA + s*32 + 8);
        cpasync16(dB0 + so, gB + s*32);
        cpasync16(dB1 + so, gB + s*32 + 8);
        cp_commit();
    }

    // -- mma fragment addressing (per-lane, swizzle-folded)
    const int wm = warp >> 2, wn = warp & 3;      // warp tile 64(M) x 32(N)
    const int quad = lane >> 3, qr = lane & 7;
    const int kq = quad >> 1;                     // k-group within ldmatrix
    const int arow0 = wm*64 + (quad & 1)*8 + qr;
    const int brow0 = wn*32 + (quad & 1)*8 + qr;
    const int xwa = (arow0 & 6) >> 1;
    const int xwb = (brow0 & 6) >> 1;
    const uint32_t aAddr = sbase + arow0*64;
    const uint32_t bAddr = sbase + ABYTES + brow0*64;

    float acc[4][4][4];
    #pragma unroll
    for (int mi = 0; mi < 4; mi++)
        #pragma unroll
        for (int ni = 0; ni < 4; ni++)
            #pragma unroll
            for (int e = 0; e < 4; e++) acc[mi][ni][e] = 0.f;

    for (int it = 0; it < KT; it++) {
        if (it <= KT - 3)      cp_wait<2>();
        else if (it == KT - 2) cp_wait<1>();
        else                   cp_wait<0>();
        __syncthreads();

        if (it + NSTAGE - 1 < KT) {
            const uint32_t so = ((it + NSTAGE - 1) & (NSTAGE-1)) * STAGE_BYTES;
            const __half* ga = gA + (it + NSTAGE - 1)*32;
            const __half* gb = gB + (it + NSTAGE - 1)*32;
            cpasync16(dA0 + so, ga);
            cpasync16(dA1 + so, ga + 8);
            cpasync16(dB0 + so, gb);
            cpasync16(dB1 + so, gb + 8);
            cp_commit();
        }

        const uint32_t so = (it & (NSTAGE-1)) * STAGE_BYTES;
        #pragma unroll
        for (int ks = 0; ks < 2; ks++) {
            uint32_t af[4][4], bf[2][4];
            #pragma unroll
            for (int mi = 0; mi < 4; mi++)
                ldsm4(af[mi], aAddr + so + mi*1024 + (((ks*2 + kq) ^ xwa) << 4));
            #pragma unroll
            for (int nb = 0; nb < 2; nb++)
                ldsm4(bf[nb], bAddr + so + nb*1024 + (((ks*2 + kq) ^ xwb) << 4));
            #pragma unroll
            for (int mi = 0; mi < 4; mi++)
                #pragma unroll
                for (int ni = 0; ni < 4; ni++) {
                    uint32_t bb[2] = { bf[ni >> 1][ni & 1], bf[ni >> 1][(ni & 1) + 2] };
                    mma_f16(acc[mi][ni], af[mi], bb);
                }
        }
        __syncthreads();
    }

    // epilogue
    const int g = lane >> 2, tg = lane & 3;
    #pragma unroll
    for (int mi = 0; mi < 4; mi++) {
        const int rb = m0 + wm*64 + mi*16 + g;
        #pragma unroll
        for (int half = 0; half < 2; half++) {
            const int r = rb + half*8;
            #pragma unroll
            for (int ni = 0; ni < 4; ni++) {
                const int c = n0 + wn*32 + ni*8 + tg*2;
                const float v0 = acc[mi][ni][half*2 + 0];
                const float v1 = acc[mi][ni][half*2 + 1];
                if (EPI == 0) {
                    float* p = (float*)outp + (size_t)r * 512 + c;
                    const float* bb = biasv + (r % 17) * 512 + c;
                    float2 o = *(float2*)p;
                    o.x += v0 + bb[0]; o.y += v1 + bb[1];
                    *(float2*)p = o;
                } else if (EPI == 1) {
                    __half2* p = (__half2*)((__half*)outp + (size_t)r * 2048 + c);
                    const float* bb = biasv + c;
                    *p = __floats2half2_rn(gelu_f(v0 + bb[0]), gelu_f(v1 + bb[1]));
                } else if (EPI == 2) {
                    float* p = (float*)outp + (size_t)r * 512 + c;
                    const float* ax = aux + (size_t)r * 512 + c;
                    const float* bb = biasv + (r % 17) * 512 + c;
                    float2 a = *(const float2*)ax;
                    float2 o;
                    o.x = a.x + v0 + bb[0]; o.y = a.y + v1 + bb[1];
                    *(float2*)p = o;
                } else {
                    float* p = (float*)outp + (size_t)r * 512 + c;
                    const float* bb = biasv + c;
                    float2 o = *(float2*)p;
                    o.x += v0 + bb[0]; o.y += v1 + bb[1];
                    *(float2*)p = o;
                }
            }
        }
    }
}

// ---------------- launch ------------------------------------------------------
extern "C" void kernel_launch(void* const* d_in, const int* in_sizes, int n_in,
                              void* d_out, int out_size)
{
    const float* x   = (const float*)d_in[0];
    const float* adj = (const float*)d_in[1];
    const float* g1  = (const float*)d_in[2];
    const float* be1 = (const float*)d_in[3];
    const float* g2  = (const float*)d_in[4];
    const float* be2 = (const float*)d_in[5];
    const float* Wg1 = (const float*)d_in[6];
    const float* bg1 = (const float*)d_in[7];
    const float* Wg2 = (const float*)d_in[8];
    const float* bg2 = (const float*)d_in[9];
    const float* W11 = (const float*)d_in[10];
    const float* b11 = (const float*)d_in[11];
    const float* W12 = (const float*)d_in[12];
    const float* b12 = (const float*)d_in[13];
    const float* W21 = (const float*)d_in[14];
    const float* b21 = (const float*)d_in[15];
    const float* W22 = (const float*)d_in[16];
    const float* b22 = (const float*)d_in[17];
    float* out = (float*)d_out;

    __half *p_xah, *p_xn2h, *p_hh, *p_Wr1h, *p_Wr2h, *p_W21h, *p_W22h;
    float *p_x2, *p_b1m, *p_b2m;
    cudaGetSymbolAddress((void**)&p_xah,  g_xah);
    cudaGetSymbolAddress((void**)&p_x2,   g_x2);
    cudaGetSymbolAddress((void**)&p_xn2h, g_xn2h);
    cudaGetSymbolAddress((void**)&p_hh,   g_hh);
    cudaGetSymbolAddress((void**)&p_Wr1h, g_Wr1h);
    cudaGetSymbolAddress((void**)&p_Wr2h, g_Wr2h);
    cudaGetSymbolAddress((void**)&p_W21h, g_W21h);
    cudaGetSymbolAddress((void**)&p_W22h, g_W22h);
    cudaGetSymbolAddress((void**)&p_b1m,  g_b1m);
    cudaGetSymbolAddress((void**)&p_b2m,  g_b2m);

    cudaFuncSetAttribute(gemm_f16<0>, cudaFuncAttributeMaxDynamicSharedMemorySize, GEMM_SMEM);
    cudaFuncSetAttribute(gemm_f16<1>, cudaFuncAttributeMaxDynamicSharedMemorySize, GEMM_SMEM);
    cudaFuncSetAttribute(gemm_f16<2>, cudaFuncAttributeMaxDynamicSharedMemorySize, GEMM_SMEM);
    cudaFuncSetAttribute(gemm_f16<3>, cudaFuncAttributeMaxDynamicSharedMemorySize, GEMM_SMEM);

    // 1) weight prep (fp16 layouts + gcn bias)
    {
        int total = 2*(Cn*KC) + 2*(Cn*CHn) + 2*(Jn*Cn);
        prep_kernel<<<(total + 255)/256, 256>>>(Wg1, Wg2, W21, W22, bg1, bg2, adj);
    }
    // 2) stage1: LN(J) + xa1(half) + fused MLP1 + residual -> g_x2 partial
    stage1_kernel<<<Bsz, 256>>>(x, adj, g1, be1, W11, b11, W12, b12);
    // 3) GCN1: g_x2 += xa1 @ Wr1^T + b1m        (M=69632, K=1536, N=512)
    gemm_f16<0><<<dim3(Cn/128, M2/128), 256, GEMM_SMEM>>>(p_xah, p_Wr1h, p_x2, p_b1m, nullptr, KC);
    // 4) LN over C -> g_xn2h (half)
    ln2_kernel<<<M2/8, 256>>>(g2, be2);
    // 5) xa2 from xn2 (reuse g_xah)
    xa2_kernel<<<(Bsz*Cn)/256, 256>>>(adj);
    // 6) MLP2 up: g_hh = half(gelu(xn2 @ W21^T + b21))   (M=69632, K=512, N=2048)
    gemm_f16<1><<<dim3(CHn/128, M2/128), 256, GEMM_SMEM>>>(p_xn2h, p_W21h, p_hh, b21, nullptr, Cn);
    // 7) GCN2: out = x2 + xa2 @ Wr2^T + b2m     (M=69632, K=1536, N=512)
    gemm_f16<2><<<dim3(Cn/128, M2/128), 256, GEMM_SMEM>>>(p_xah, p_Wr2h, out, p_b2m, p_x2, KC);
    // 8) MLP2 down: out += h @ W22^T + b22      (M=69632, K=2048, N=512)
    gemm_f16<3><<<dim3(Cn/128, M2/128), 256, GEMM_SMEM>>>(p_hh, p_W22h, out, b22, nullptr, CHn);
}

// round 5
// speedup vs baseline: 3.8000x; 1.1991x over previous
#include <cuda_runtime.h>
#include <cuda_fp16.h>
#include <math.h>
#include <stdint.h>

// Problem constants
#define Bsz 4096
#define Jn  17
#define Cn  512
#define Kn  3
#define TOKn 256
#define CHn 2048
#define M2  (Bsz*Jn)       // 69632
#define KC  (Kn*Cn)        // 1536
#define KCAT (KC + CHn)    // 3584
#define MR  (Bsz*Cn)       // 2097152 rows of (b,c)
#define EPSF 1e-5f

// ---------------- scratch (device globals; allocation-free rule) -------------
__device__ __half g_xah [M2 * KC];        // xa1, fp16                (214 MB)
__device__ float  g_x2  [Bsz*Jn*Cn];      // stage-1 result, fp32     (143 MB)
__device__ __half g_xn2h[Bsz*Jn*Cn];      // LN2 output, fp16         (71 MB)
__device__ __half g_cat [(size_t)M2 * KCAT]; // [xa2 | h], fp16       (499 MB)
__device__ __half g_xnh [(size_t)MR * 32];   // LN1 xn, K-padded      (134 MB)
__device__ __half g_Wr1h[Cn * KC];        // [o][k*512+c]
__device__ __half g_Wcat[Cn * KCAT];      // [o][Wr2 | W22]
__device__ __half g_W21h[CHn * Cn];       // [ch][c]
__device__ __half g_W11h[TOKn * 32];      // [t][j pad 32]
__device__ __half g_W12h[32 * TOKn];      // [j pad 32][t]
__device__ float  g_b1m [Jn * Cn];
__device__ float  g_b2m [Jn * Cn];        // includes b22

__device__ __forceinline__ float gelu_f(float v) {
    return 0.5f * v * (1.0f + erff(v * 0.7071067811865476f));
}

// ---------------- PTX helpers ------------------------------------------------
__device__ __forceinline__ void mma_f16(float* d, const uint32_t* a, const uint32_t* b) {
    asm volatile(
        "mma.sync.aligned.m16n8k16.row.col.f32.f16.f16.f32 "
        "{%0,%1,%2,%3}, {%4,%5,%6,%7}, {%8,%9}, {%0,%1,%2,%3};"
        : "+f"(d[0]), "+f"(d[1]), "+f"(d[2]), "+f"(d[3])
        : "r"(a[0]), "r"(a[1]), "r"(a[2]), "r"(a[3]), "r"(b[0]), "r"(b[1]));
}
__device__ __forceinline__ void ldsm4(uint32_t* r, uint32_t addr) {
    asm volatile("ldmatrix.sync.aligned.m8n8.x4.shared.b16 {%0,%1,%2,%3}, [%4];"
                 : "=r"(r[0]), "=r"(r[1]), "=r"(r[2]), "=r"(r[3]) : "r"(addr));
}
__device__ __forceinline__ void cpasync16(uint32_t smem, const void* g) {
    asm volatile("cp.async.cg.shared.global [%0], [%1], 16;" :: "r"(smem), "l"(g));
}
__device__ __forceinline__ void cp_commit() {
    asm volatile("cp.async.commit_group;" ::: "memory");
}
template<int N_> __device__ __forceinline__ void cp_wait() {
    asm volatile("cp.async.wait_group %0;" :: "n"(N_) : "memory");
}
__device__ __forceinline__ uint32_t h2u(__half2 h) { return *(uint32_t*)&h; }

// ---------------- prep: weight layouts (fp16) + gcn bias ---------------------
__global__ void prep_kernel(const float* __restrict__ Wg1, const float* __restrict__ Wg2,
                            const float* __restrict__ W21, const float* __restrict__ W22,
                            const float* __restrict__ bg1, const float* __restrict__ bg2,
                            const float* __restrict__ adj,
                            const float* __restrict__ W11, const float* __restrict__ W12,
                            const float* __restrict__ b22)
{
    int i = blockIdx.x * 256 + threadIdx.x;
    const int S_Wr1 = Cn * KC;        // 786432
    const int S_Wcat = Cn * KCAT;     // 1835008
    const int S_W21 = CHn * Cn;       // 1048576
    if (i < S_Wr1) {                  // Wr1[o][k*512+c] = Wg1[k][o][c]
        int o = i / KC, rem = i % KC;
        int k = rem >> 9, c = rem & 511;
        g_Wr1h[i] = __float2half_rn(Wg1[k * (Cn*Cn) + o * Cn + c]);
        return;
    }
    i -= S_Wr1;
    if (i < S_Wcat) {                 // Wcat[o][0:1536]=Wr2, [1536:]=W22[o][ch]
        int o = i / KCAT, kk = i % KCAT;
        float v;
        if (kk < KC) {
            int k = kk >> 9, c = kk & 511;
            v = Wg2[k * (Cn*Cn) + o * Cn + c];
        } else {
            v = W22[o * CHn + (kk - KC)];
        }
        g_Wcat[i] = __float2half_rn(v);
        return;
    }
    i -= S_Wcat;
    if (i < S_W21) { g_W21h[i] = __float2half_rn(W21[i]); return; }   // [ch][c]
    i -= S_W21;
    if (i < TOKn * 32) {              // W11p[t][j pad 32]
        int t = i >> 5, j = i & 31;
        g_W11h[i] = (j < Jn) ? __float2half_rn(W11[t * Jn + j]) : __half(0.f);
        return;
    }
    i -= TOKn * 32;
    if (i < 32 * TOKn) {              // W12p[j pad 32][t]
        int n = i >> 8, t = i & 255;
        g_W12h[i] = (n < Jn) ? __float2half_rn(W12[n * TOKn + t]) : __half(0.f);
        return;
    }
    i -= 32 * TOKn;
    if (i < Jn * Cn) {                // b1m
        int w = i >> 9, o = i & 511;
        float s = 0.f;
        #pragma unroll
        for (int k = 0; k < Kn; k++) {
            float cs = 0.f;
            #pragma unroll
            for (int v = 0; v < Jn; v++) cs += adj[k*289 + v*17 + w];
            s += bg1[k * Cn + o] * cs;
        }
        g_b1m[i] = s;
        return;
    }
    i -= Jn * Cn;
    if (i < Jn * Cn) {                // b2m (+ b22)
        int w = i >> 9, o = i & 511;
        float s = b22[o];
        #pragma unroll
        for (int k = 0; k < Kn; k++) {
            float cs = 0.f;
            #pragma unroll
            for (int v = 0; v < Jn; v++) cs += adj[k*289 + v*17 + w];
            s += bg2[k * Cn + o] * cs;
        }
        g_b2m[i] = s;
        return;
    }
}

// ---------------- stage 1: LN(J) -> xa1(fp16) + xnh(fp16, Kpad32) ------------
__global__ __launch_bounds__(256) void stage1_kernel(
    const float* __restrict__ x, const float* __restrict__ adj,
    const float* __restrict__ g1, const float* __restrict__ be1)
{
    __shared__ float sadjT[Kn * Jn * 18];
    __shared__ float sg1[Jn], sbe1[Jn];

    const int tid = threadIdx.x;
    const int b = blockIdx.x;

    for (int i = tid; i < Kn*Jn*Jn; i += 256) { int k = i/289, r = i%289, v = r/17, w = r%17; sadjT[(k*17+w)*18 + v] = adj[i]; }
    for (int i = tid; i < Kn*Jn; i += 256) sadjT[i*18 + 17] = 0.f;
    if (tid < Jn) { sg1[tid] = g1[tid]; sbe1[tid] = be1[tid]; }
    __syncthreads();

    const int c0 = tid, c1 = tid + 256;
    const float* xb = x + (size_t)b * (Jn*Cn);

    float xr0[Jn], xr1[Jn];
    #pragma unroll
    for (int j = 0; j < Jn; j++) { xr0[j] = xb[j*Cn + c0]; xr1[j] = xb[j*Cn + c1]; }

    float mu0 = 0.f, mu1 = 0.f;
    #pragma unroll
    for (int j = 0; j < Jn; j++) { mu0 += xr0[j]; mu1 += xr1[j]; }
    mu0 *= (1.0f/17.0f); mu1 *= (1.0f/17.0f);
    float v0 = 0.f, v1 = 0.f;
    #pragma unroll
    for (int j = 0; j < Jn; j++) { float d0 = xr0[j]-mu0, d1 = xr1[j]-mu1; v0 += d0*d0; v1 += d1*d1; }
    float rs0 = rsqrtf(v0*(1.0f/17.0f) + EPSF);
    float rs1 = rsqrtf(v1*(1.0f/17.0f) + EPSF);

    float xn0[18], xn1[18];
    #pragma unroll
    for (int j = 0; j < Jn; j++) {
        xn0[j] = (xr0[j]-mu0)*rs0*sg1[j] + sbe1[j];
        xn1[j] = (xr1[j]-mu1)*rs1*sg1[j] + sbe1[j];
    }
    xn0[17] = 0.f; xn1[17] = 0.f;

    // xa1 (fp16)
    #pragma unroll
    for (int k = 0; k < Kn; k++) {
        #pragma unroll
        for (int w = 0; w < Jn; w++) {
            const float2* ar = (const float2*)&sadjT[(k*17+w)*18];
            float s0 = 0.f, s1 = 0.f;
            #pragma unroll
            for (int p = 0; p < 9; p++) {
                float2 a = ar[p];
                s0 += a.x*xn0[2*p] + a.y*xn0[2*p+1];
                s1 += a.x*xn1[2*p] + a.y*xn1[2*p+1];
            }
            int idx = (b*17 + w)*KC + k*Cn;
            g_xah[idx + c0] = __float2half_rn(s0);
            g_xah[idx + c1] = __float2half_rn(s1);
        }
    }

    // xnh rows (b*512+c), 32 halves each (cols 17..31 zero)
    {
        __half2 hx[16];
        #pragma unroll
        for (int p = 0; p < 8; p++) hx[p] = __floats2half2_rn(xn0[2*p], xn0[2*p+1]);
        hx[8] = __floats2half2_rn(xn0[16], 0.f);
        #pragma unroll
        for (int p = 9; p < 16; p++) hx[p] = __floats2half2_rn(0.f, 0.f);
        uint4* dst = (uint4*)(g_xnh + ((size_t)b*512 + c0) * 32);
        const uint4* s = (const uint4*)hx;
        dst[0] = s[0]; dst[1] = s[1]; dst[2] = s[2]; dst[3] = s[3];

        #pragma unroll
        for (int p = 0; p < 8; p++) hx[p] = __floats2half2_rn(xn1[2*p], xn1[2*p+1]);
        hx[8] = __floats2half2_rn(xn1[16], 0.f);
        uint4* dst1 = (uint4*)(g_xnh + ((size_t)b*512 + c1) * 32);
        dst1[0] = s[0]; dst1[1] = s[1]; dst1[2] = s[2]; dst1[3] = s[3];
    }
}

// ---------------- fused MLP1 on tensor cores ---------------------------------
// x2[b][j][c] = x[b][j][c] + (gelu(xn @ W11^T + b11) @ W12^T)[j] + b12[j]
// 128 rows (b,c) per CTA, 8 warps x 16 rows. GEMM1 d-frag == GEMM2 a-frag.
#define M1_XN   0            // [128][80B]   10240
#define M1_W11  10240        // [256][80B]   20480
#define M1_W12  30720        // [32][512B]   16384 (swizzled)
#define M1_B11  47104        // 256 floats
#define M1_B12  48128        // 17 floats
#define M1_SMEM 48256

__global__ __launch_bounds__(256, 2) void mlp1_kernel(
    const float* __restrict__ x,
    const float* __restrict__ b11, const float* __restrict__ b12)
{
    extern __shared__ __align__(128) char sm[];
    uint32_t sbase;
    asm("{ .reg .u64 t; cvta.to.shared.u64 t, %1; cvt.u32.u64 %0, t; }" : "=r"(sbase) : "l"(sm));
    float* sb11 = (float*)(sm + M1_B11);
    float* sb12 = (float*)(sm + M1_B12);

    const int tid = threadIdx.x, warp = tid >> 5, lane = tid & 31;
    const int rb = blockIdx.x * 128;

    // loads
    {   // xnh tile: rows rb..rb+127, 64B each -> pitch 80
        const int r = tid >> 1;
        const __half* src = g_xnh + ((size_t)(rb + r)) * 32;
        const uint32_t dst = sbase + M1_XN + r*80;
        const int c0 = (tid & 1) * 2;
        cpasync16(dst + (c0+0)*16, src + (c0+0)*8);
        cpasync16(dst + (c0+1)*16, src + (c0+1)*8);
    }
    #pragma unroll
    for (int i = 0; i < 4; i++) {   // W11p: 1024 chunks, pitch 80
        int ci = tid + 256*i;
        int row = ci >> 2, g = ci & 3;
        cpasync16(sbase + M1_W11 + row*80 + g*16, g_W11h + row*32 + g*8);
    }
    #pragma unroll
    for (int i = 0; i < 4; i++) {   // W12p: 1024 chunks, 512B rows, swizzled
        int ci = tid + 256*i;
        int row = ci >> 5, g = ci & 31;
        int gp = (g & ~7) | ((g ^ row) & 7);
        cpasync16(sbase + M1_W12 + row*512 + gp*16, g_W12h + row*256 + g*8);
    }
    cp_commit();
    sb11[tid] = b11[tid];
    if (tid < Jn) sb12[tid] = b12[tid];
    cp_wait<0>();
    __syncthreads();

    const int quad = lane >> 3, qr = lane & 7;
    const int kq = quad >> 1, qh = quad & 1;
    const int g = lane >> 2, tg = lane & 3;

    // A-frags for GEMM1 (k=32 -> 2 k-steps), persist
    uint32_t af[2][4];
    {
        const uint32_t aAddr = sbase + M1_XN + (warp*16 + qh*8 + qr)*80;
        ldsm4(af[0], aAddr + ((0*2 + kq) << 4));
        ldsm4(af[1], aAddr + ((1*2 + kq) << 4));
    }

    float oacc[3][4];
    #pragma unroll
    for (int n = 0; n < 3; n++)
        #pragma unroll
        for (int e = 0; e < 4; e++) oacc[n][e] = 0.f;

    #pragma unroll
    for (int q = 0; q < 4; q++) {
        float hacc[8][4];
        #pragma unroll
        for (int n = 0; n < 8; n++)
            #pragma unroll
            for (int e = 0; e < 4; e++) hacc[n][e] = 0.f;

        // GEMM1: hidden cols [64q, 64q+64)
        #pragma unroll
        for (int nb = 0; nb < 4; nb++) {
            const uint32_t bAddr = sbase + M1_W11 + (q*64 + nb*16 + qh*8 + qr)*80;
            #pragma unroll
            for (int ks = 0; ks < 2; ks++) {
                uint32_t bf[4];
                ldsm4(bf, bAddr + ((ks*2 + kq) << 4));
                #pragma unroll
                for (int ni = 0; ni < 2; ni++) {
                    uint32_t bb[2] = { bf[ni], bf[ni + 2] };
                    mma_f16(hacc[nb*2 + ni], af[ks], bb);
                }
            }
        }

        // bias + gelu + pack (d-frag -> a-frag)
        uint32_t h2[8][2];
        #pragma unroll
        for (int nt = 0; nt < 8; nt++) {
            int t0 = q*64 + nt*8 + tg*2;
            float b0 = sb11[t0], b1 = sb11[t0 + 1];
            h2[nt][0] = h2u(__floats2half2_rn(gelu_f(hacc[nt][0] + b0), gelu_f(hacc[nt][1] + b1)));
            h2[nt][1] = h2u(__floats2half2_rn(gelu_f(hacc[nt][2] + b0), gelu_f(hacc[nt][3] + b1)));
        }

        // GEMM2 partial: k-steps 4q..4q+3
        #pragma unroll
        for (int ksl = 0; ksl < 4; ksl++) {
            uint32_t a2[4] = { h2[2*ksl][0], h2[2*ksl][1], h2[2*ksl+1][0], h2[2*ksl+1][1] };
            int kgrp = (q*4 + ksl)*2 + kq;
            #pragma unroll
            for (int nb2 = 0; nb2 < 2; nb2++) {
                const int brow = nb2*16 + qh*8 + qr;
                int gp = (kgrp & ~7) | ((kgrp ^ brow) & 7);
                uint32_t bf[4];
                ldsm4(bf, sbase + M1_W12 + brow*512 + (gp << 4));
                #pragma unroll
                for (int ni = 0; ni < 2; ni++) {
                    int nt2 = nb2*2 + ni;
                    if (nt2 < 3) {
                        uint32_t bb[2] = { bf[ni], bf[ni + 2] };
                        mma_f16(oacc[nt2], a2, bb);
                    }
                }
            }
        }
    }

    // epilogue: x2 = x + mlp1 + b12 (rows (b,c), cols j)
    #pragma unroll
    for (int nt2 = 0; nt2 < 3; nt2++) {
        #pragma unroll
        for (int e = 0; e < 4; e++) {
            int j = nt2*8 + tg*2 + (e & 1);
            if (j < Jn) {
                int rowg = rb + warp*16 + g + ((e >> 1) * 8);
                int b = rowg >> 9, c = rowg & 511;
                size_t idx = ((size_t)b*17 + j)*512 + c;
                g_x2[idx] = x[idx] + oacc[nt2][e] + sb12[j];
            }
        }
    }
}

// ---------------- LN over C=512 (one warp per row), fp16 out -----------------
__global__ __launch_bounds__(256) void ln2_kernel(const float* __restrict__ g2,
                                                  const float* __restrict__ be2)
{
    int row = blockIdx.x * 8 + (threadIdx.x >> 5);
    int lane = threadIdx.x & 31;
    const float4* xr = (const float4*)(g_x2 + (size_t)row * Cn);
    float4 a0 = xr[lane], a1 = xr[lane+32], a2 = xr[lane+64], a3 = xr[lane+96];
    float s = a0.x+a0.y+a0.z+a0.w + a1.x+a1.y+a1.z+a1.w
            + a2.x+a2.y+a2.z+a2.w + a3.x+a3.y+a3.z+a3.w;
    #pragma unroll
    for (int off = 16; off; off >>= 1) s += __shfl_xor_sync(0xffffffffu, s, off);
    float mu = s * (1.0f/512.0f);
    float q = 0.f;
    {
        float d;
        d=a0.x-mu; q+=d*d; d=a0.y-mu; q+=d*d; d=a0.z-mu; q+=d*d; d=a0.w-mu; q+=d*d;
        d=a1.x-mu; q+=d*d; d=a1.y-mu; q+=d*d; d=a1.z-mu; q+=d*d; d=a1.w-mu; q+=d*d;
        d=a2.x-mu; q+=d*d; d=a2.y-mu; q+=d*d; d=a2.z-mu; q+=d*d; d=a2.w-mu; q+=d*d;
        d=a3.x-mu; q+=d*d; d=a3.y-mu; q+=d*d; d=a3.z-mu; q+=d*d; d=a3.w-mu; q+=d*d;
    }
    #pragma unroll
    for (int off = 16; off; off >>= 1) q += __shfl_xor_sync(0xffffffffu, q, off);
    float rstd = rsqrtf(q * (1.0f/512.0f) + EPSF);

    const float4* gg = (const float4*)g2;
    const float4* bb = (const float4*)be2;
    __half2* oh = (__half2*)(g_xn2h + (size_t)row * Cn);
    #pragma unroll
    for (int i = 0; i < 4; i++) {
        float4 a = (i==0)?a0:(i==1)?a1:(i==2)?a2:a3;
        float4 g = gg[lane + i*32], e = bb[lane + i*32];
        int p = (lane + i*32) * 2;
        oh[p]   = __floats2half2_rn((a.x-mu)*rstd*g.x + e.x, (a.y-mu)*rstd*g.y + e.y);
        oh[p+1] = __floats2half2_rn((a.z-mu)*rstd*g.z + e.z, (a.w-mu)*rstd*g.w + e.w);
    }
}

// ---------------- xa2 from xn2 -> g_cat[:, 0:1536] ---------------------------
__global__ __launch_bounds__(256) void xa2_kernel(const float* __restrict__ adj)
{
    __shared__ float sadjT[Kn * Jn * 18];
    int tid = threadIdx.x;
    for (int i = tid; i < Kn*Jn*Jn; i += 256) { int k = i/289, r = i%289, v = r/17, w = r%17; sadjT[(k*17+w)*18 + v] = adj[i]; }
    for (int i = tid; i < Kn*Jn; i += 256) sadjT[i*18 + 17] = 0.f;
    __syncthreads();

    int gi = blockIdx.x * 256 + tid;
    int b = gi >> 9, c = gi & 511;
    float xv[18];
    #pragma unroll
    for (int v = 0; v < Jn; v++) xv[v] = __half2float(g_xn2h[(size_t)b*(Jn*Cn) + v*Cn + c]);
    xv[17] = 0.f;
    #pragma unroll
    for (int k = 0; k < Kn; k++) {
        #pragma unroll
        for (int w = 0; w < Jn; w++) {
            const float2* ar = (const float2*)&sadjT[(k*17+w)*18];
            float s = 0.f;
            #pragma unroll
            for (int p = 0; p < 9; p++) { float2 a = ar[p]; s += a.x*xv[2*p] + a.y*xv[2*p+1]; }
            g_cat[(size_t)(b*17 + w)*KCAT + k*Cn + c] = __float2half_rn(s);
        }
    }
}

// ---------------- fp16 tensor-core GEMM, 128x128x32, 4-stage cp.async --------
// A: [M][Kd] half row-major. Bw: [N][Kd] half row-major. acc = A @ Bw^T (fp32).
// EPI 0: x2 += acc + b1m[(r%17)*512+c]                  (float out, stride 512)
// EPI 1: g_cat[r][1536+c] = half(gelu(acc + biasv[c]))  (half out, stride 3584)
// EPI 2: out = aux + acc + b2m[(r%17)*512+c]            (float out, stride 512)
#define NSTAGE 4
#define ABYTES 8192                      // 128 rows x 64 B
#define STAGE_BYTES (2*ABYTES)           // 16384
#define GEMM_SMEM (NSTAGE*STAGE_BYTES)   // 65536

template<int EPI>
__global__ __launch_bounds__(256, 2) void gemm_f16(
    const __half* __restrict__ A, const __half* __restrict__ Bw,
    void* __restrict__ outp, const float* __restrict__ biasv,
    const float* __restrict__ aux, int Kd)
{
    extern __shared__ __align__(128) char smem[];
    uint32_t sbase;
    asm("{ .reg .u64 t; cvta.to.shared.u64 t, %1; cvt.u32.u64 %0, t; }" : "=r"(sbase) : "l"(smem));

    const int tid  = threadIdx.x;
    const int warp = tid >> 5;
    const int lane = tid & 31;
    const int m0 = blockIdx.y * 128;
    const int n0 = blockIdx.x * 128;
    const int KT = Kd >> 5;

    const int lrow = tid >> 1;
    const int gsel = tid & 1;
    const int xw   = (lrow & 6) >> 1;
    const __half* gA = A  + (size_t)(m0 + lrow) * Kd + gsel * 16;
    const __half* gB = Bw + (size_t)(n0 + lrow) * Kd + gsel * 16;
    const uint32_t dA0 = sbase + lrow*64 + (((gsel*2 + 0) ^ xw) << 4);
    const uint32_t dA1 = sbase + lrow*64 + (((gsel*2 + 1) ^ xw) << 4);
    const uint32_t dB0 = dA0 + ABYTES;
    const uint32_t dB1 = dA1 + ABYTES;

    #pragma unroll
    for (int s = 0; s < NSTAGE - 1; s++) {
        const uint32_t so = s * STAGE_BYTES;
        cpasync16(dA0 + so, gA + s*32);
        cpasync16(dA1 + so, gA + s*32 + 8);
        cpasync16(dB0 + so, gB + s*32);
        cpasync16(dB1 + so, gB + s*32 + 8);
        cp_commit();
    }

    const int wm = warp >> 2, wn = warp & 3;
    const int quad = lane >> 3, qr = lane & 7;
    const int kq = quad >> 1;
    const int arow0 = wm*64 + (quad & 1)*8 + qr;
    const int brow0 = wn*32 + (quad & 1)*8 + qr;
    const int xwa = (arow0 & 6) >> 1;
    const int xwb = (brow0 & 6) >> 1;
    const uint32_t aAddr = sbase + arow0*64;
    const uint32_t bAddr = sbase + ABYTES + brow0*64;

    float acc[4][4][4];
    #pragma unroll
    for (int mi = 0; mi < 4; mi++)
        #pragma unroll
        for (int ni = 0; ni < 4; ni++)
            #pragma unroll
            for (int e = 0; e < 4; e++) acc[mi][ni][e] = 0.f;

    for (int it = 0; it < KT; it++) {
        if (it <= KT - 3)      cp_wait<2>();
        else if (it == KT - 2) cp_wait<1>();
        else                   cp_wait<0>();
        __syncthreads();

        if (it + NSTAGE - 1 < KT) {
            const uint32_t so = ((it + NSTAGE - 1) & (NSTAGE-1)) * STAGE_BYTES;
            const __half* ga = gA + (it + NSTAGE - 1)*32;
            const __half* gb = gB + (it + NSTAGE - 1)*32;
            cpasync16(dA0 + so, ga);
            cpasync16(dA1 + so, ga + 8);
            cpasync16(dB0 + so, gb);
            cpasync16(dB1 + so, gb + 8);
            cp_commit();
        }

        const uint32_t so = (it & (NSTAGE-1)) * STAGE_BYTES;
        #pragma unroll
        for (int ks = 0; ks < 2; ks++) {
            uint32_t af[4][4], bf[2][4];
            #pragma unroll
            for (int mi = 0; mi < 4; mi++)
                ldsm4(af[mi], aAddr + so + mi*1024 + (((ks*2 + kq) ^ xwa) << 4));
            #pragma unroll
            for (int nb = 0; nb < 2; nb++)
                ldsm4(bf[nb], bAddr + so + nb*1024 + (((ks*2 + kq) ^ xwb) << 4));
            #pragma unroll
            for (int mi = 0; mi < 4; mi++)
                #pragma unroll
                for (int ni = 0; ni < 4; ni++) {
                    uint32_t bb[2] = { bf[ni >> 1][ni & 1], bf[ni >> 1][(ni & 1) + 2] };
                    mma_f16(acc[mi][ni], af[mi], bb);
                }
        }
        __syncthreads();
    }

    const int g = lane >> 2, tg = lane & 3;
    #pragma unroll
    for (int mi = 0; mi < 4; mi++) {
        const int rbm = m0 + wm*64 + mi*16 + g;
        #pragma unroll
        for (int half = 0; half < 2; half++) {
            const int r = rbm + half*8;
            #pragma unroll
            for (int ni = 0; ni < 4; ni++) {
                const int c = n0 + wn*32 + ni*8 + tg*2;
                const float v0 = acc[mi][ni][half*2 + 0];
                const float v1 = acc[mi][ni][half*2 + 1];
                if (EPI == 0) {
                    float* p = (float*)outp + (size_t)r * 512 + c;
                    const float* bb = biasv + (r % 17) * 512 + c;
                    float2 o = *(float2*)p;
                    o.x += v0 + bb[0]; o.y += v1 + bb[1];
                    *(float2*)p = o;
                } else if (EPI == 1) {
                    __half2* p = (__half2*)((__half*)outp + (size_t)r * KCAT + KC + c);
                    const float* bb = biasv + c;
                    *p = __floats2half2_rn(gelu_f(v0 + bb[0]), gelu_f(v1 + bb[1]));
                } else {
                    float* p = (float*)outp + (size_t)r * 512 + c;
                    const float* ax = aux + (size_t)r * 512 + c;
                    const float* bb = biasv + (r % 17) * 512 + c;
                    float2 a = *(const float2*)ax;
                    float2 o;
                    o.x = a.x + v0 + bb[0]; o.y = a.y + v1 + bb[1];
                    *(float2*)p = o;
                }
            }
        }
    }
}

// ---------------- launch ------------------------------------------------------
extern "C" void kernel_launch(void* const* d_in, const int* in_sizes, int n_in,
                              void* d_out, int out_size)
{
    const float* x   = (const float*)d_in[0];
    const float* adj = (const float*)d_in[1];
    const float* g1  = (const float*)d_in[2];
    const float* be1 = (const float*)d_in[3];
    const float* g2  = (const float*)d_in[4];
    const float* be2 = (const float*)d_in[5];
    const float* Wg1 = (const float*)d_in[6];
    const float* bg1 = (const float*)d_in[7];
    const float* Wg2 = (const float*)d_in[8];
    const float* bg2 = (const float*)d_in[9];
    const float* W11 = (const float*)d_in[10];
    const float* b11 = (const float*)d_in[11];
    const float* W12 = (const float*)d_in[12];
    const float* b12 = (const float*)d_in[13];
    const float* W21 = (const float*)d_in[14];
    const float* b21 = (const float*)d_in[15];
    const float* W22 = (const float*)d_in[16];
    const float* b22 = (const float*)d_in[17];
    float* out = (float*)d_out;

    __half *p_xah, *p_xn2h, *p_cat, *p_Wr1h, *p_Wcat, *p_W21h;
    float *p_x2, *p_b1m, *p_b2m;
    cudaGetSymbolAddress((void**)&p_xah,  g_xah);
    cudaGetSymbolAddress((void**)&p_x2,   g_x2);
    cudaGetSymbolAddress((void**)&p_xn2h, g_xn2h);
    cudaGetSymbolAddress((void**)&p_cat,  g_cat);
    cudaGetSymbolAddress((void**)&p_Wr1h, g_Wr1h);
    cudaGetSymbolAddress((void**)&p_Wcat, g_Wcat);
    cudaGetSymbolAddress((void**)&p_W21h, g_W21h);
    cudaGetSymbolAddress((void**)&p_b1m,  g_b1m);
    cudaGetSymbolAddress((void**)&p_b2m,  g_b2m);

    cudaFuncSetAttribute(gemm_f16<0>, cudaFuncAttributeMaxDynamicSharedMemorySize, GEMM_SMEM);
    cudaFuncSetAttribute(gemm_f16<1>, cudaFuncAttributeMaxDynamicSharedMemorySize, GEMM_SMEM);
    cudaFuncSetAttribute(gemm_f16<2>, cudaFuncAttributeMaxDynamicSharedMemorySize, GEMM_SMEM);
    cudaFuncSetAttribute(mlp1_kernel, cudaFuncAttributeMaxDynamicSharedMemorySize, M1_SMEM);

    // 1) weight prep
    {
        int total = Cn*KC + Cn*KCAT + CHn*Cn + TOKn*32 + 32*TOKn + 2*(Jn*Cn);
        prep_kernel<<<(total + 255)/256, 256>>>(Wg1, Wg2, W21, W22, bg1, bg2, adj, W11, W12, b22);
    }
    // 2) stage1: LN(J) -> xa1 + xnh
    stage1_kernel<<<Bsz, 256>>>(x, adj, g1, be1);
    // 3) fused tensor MLP1: x2 = x + mlp1(xn) + b12
    mlp1_kernel<<<MR/128, 256, M1_SMEM>>>(x, b11, b12);
    // 4) GCN1: x2 += xa1 @ Wr1^T + b1m       (M=69632, K=1536, N=512)
    gemm_f16<0><<<dim3(Cn/128, M2/128), 256, GEMM_SMEM>>>(p_xah, p_Wr1h, p_x2, p_b1m, nullptr, KC);
    // 5) LN over C -> g_xn2h
    ln2_kernel<<<M2/8, 256>>>(g2, be2);
    // 6) xa2 -> g_cat[:, 0:1536]
    xa2_kernel<<<(Bsz*Cn)/256, 256>>>(adj);
    // 7) MLP2 up: g_cat[:, 1536:] = half(gelu(xn2 @ W21^T + b21))  (K=512, N=2048)
    gemm_f16<1><<<dim3(CHn/128, M2/128), 256, GEMM_SMEM>>>(p_xn2h, p_W21h, p_cat, b21, nullptr, Cn);
    // 8) final fused GCN2+MLP2dn: out = x2 + cat @ Wcat^T + b2m'   (K=3584, N=512)
    gemm_f16<2><<<dim3(Cn/128, M2/128), 256, GEMM_SMEM>>>(p_cat, p_Wcat, out, p_b2m, p_x2, KCAT);
}

// round 6
// speedup vs baseline: 3.8810x; 1.0213x over previous
#include <cuda_runtime.h>
#include <cuda_fp16.h>
#include <math.h>
#include <stdint.h>

// Problem constants
#define Bsz 4096
#define Jn  17
#define Cn  512
#define Kn  3
#define TOKn 256
#define CHn 2048
#define M2  (Bsz*Jn)       // 69632
#define KC  (Kn*Cn)        // 1536
#define KCAT (KC + CHn)    // 3584
#define MR  (Bsz*Cn)       // 2097152 rows of (b,c)
#define EPSF 1e-5f

// ---------------- scratch (device globals; allocation-free rule) -------------
__device__ __half g_xah [M2 * KC];        // xa1, fp16                (214 MB)
__device__ float  g_x2  [Bsz*Jn*Cn];      // stage-1 result, fp32     (143 MB)
__device__ __half g_xn2h[Bsz*Jn*Cn];      // LN2 output, fp16         (71 MB)
__device__ __half g_cat [(size_t)M2 * KCAT]; // [xa2 | h], fp16       (499 MB)
__device__ __half g_xnh [(size_t)MR * 16];   // LN1 xn, k=16          (67 MB)
__device__ __half g_xn16[(size_t)MR];        // LN1 xn element 16     (4 MB)
__device__ __half g_Wr1h[Cn * KC];        // [o][k*512+c]
__device__ __half g_Wcat[Cn * KCAT];      // [o][Wr2 | W22]
__device__ __half g_W21h[CHn * Cn];       // [ch][c]
__device__ __half g_W11h[TOKn * 16];      // [t][j 0..15]
__device__ float  g_w11c16[TOKn];         // W11[t][16]
__device__ __half g_W12h[32 * TOKn];      // [j pad 32][t]
__device__ float  g_b1m [Jn * Cn];
__device__ float  g_b2m [Jn * Cn];        // includes b22

__device__ __forceinline__ float gelu_f(float v) {
    return 0.5f * v * (1.0f + erff(v * 0.7071067811865476f));
}

// ---------------- PTX helpers ------------------------------------------------
__device__ __forceinline__ void mma_f16(float* d, const uint32_t* a, const uint32_t* b) {
    asm volatile(
        "mma.sync.aligned.m16n8k16.row.col.f32.f16.f16.f32 "
        "{%0,%1,%2,%3}, {%4,%5,%6,%7}, {%8,%9}, {%0,%1,%2,%3};"
        : "+f"(d[0]), "+f"(d[1]), "+f"(d[2]), "+f"(d[3])
        : "r"(a[0]), "r"(a[1]), "r"(a[2]), "r"(a[3]), "r"(b[0]), "r"(b[1]));
}
__device__ __forceinline__ void ldsm4(uint32_t* r, uint32_t addr) {
    asm volatile("ldmatrix.sync.aligned.m8n8.x4.shared.b16 {%0,%1,%2,%3}, [%4];"
                 : "=r"(r[0]), "=r"(r[1]), "=r"(r[2]), "=r"(r[3]) : "r"(addr));
}
__device__ __forceinline__ void cpasync16(uint32_t smem, const void* g) {
    asm volatile("cp.async.cg.shared.global [%0], [%1], 16;" :: "r"(smem), "l"(g));
}
__device__ __forceinline__ void cp_commit() {
    asm volatile("cp.async.commit_group;" ::: "memory");
}
template<int N_> __device__ __forceinline__ void cp_wait() {
    asm volatile("cp.async.wait_group %0;" :: "n"(N_) : "memory");
}
__device__ __forceinline__ uint32_t h2u(__half2 h) { return *(uint32_t*)&h; }

// ---------------- prep: weight layouts (fp16) + gcn bias ---------------------
__global__ void prep_kernel(const float* __restrict__ Wg1, const float* __restrict__ Wg2,
                            const float* __restrict__ W21, const float* __restrict__ W22,
                            const float* __restrict__ bg1, const float* __restrict__ bg2,
                            const float* __restrict__ adj,
                            const float* __restrict__ W11, const float* __restrict__ W12,
                            const float* __restrict__ b22)
{
    int i = blockIdx.x * 256 + threadIdx.x;
    const int S_Wr1 = Cn * KC;        // 786432
    const int S_Wcat = Cn * KCAT;     // 1835008
    const int S_W21 = CHn * Cn;       // 1048576
    if (i < S_Wr1) {                  // Wr1[o][k*512+c] = Wg1[k][o][c]
        int o = i / KC, rem = i % KC;
        int k = rem >> 9, c = rem & 511;
        g_Wr1h[i] = __float2half_rn(Wg1[k * (Cn*Cn) + o * Cn + c]);
        return;
    }
    i -= S_Wr1;
    if (i < S_Wcat) {                 // Wcat[o][0:1536]=Wr2, [1536:]=W22[o][ch]
        int o = i / KCAT, kk = i % KCAT;
        float v;
        if (kk < KC) {
            int k = kk >> 9, c = kk & 511;
            v = Wg2[k * (Cn*Cn) + o * Cn + c];
        } else {
            v = W22[o * CHn + (kk - KC)];
        }
        g_Wcat[i] = __float2half_rn(v);
        return;
    }
    i -= S_Wcat;
    if (i < S_W21) { g_W21h[i] = __float2half_rn(W21[i]); return; }   // [ch][c]
    i -= S_W21;
    if (i < TOKn * 16) {              // W11p[t][j 0..15]
        int t = i >> 4, j = i & 15;
        g_W11h[i] = __float2half_rn(W11[t * Jn + j]);
        return;
    }
    i -= TOKn * 16;
    if (i < TOKn) {                   // W11 column 16 (float)
        g_w11c16[i] = W11[i * Jn + 16];
        return;
    }
    i -= TOKn;
    if (i < 32 * TOKn) {              // W12p[j pad 32][t]
        int n = i >> 8, t = i & 255;
        g_W12h[i] = (n < Jn) ? __float2half_rn(W12[n * TOKn + t]) : __half(0.f);
        return;
    }
    i -= 32 * TOKn;
    if (i < Jn * Cn) {                // b1m
        int w = i >> 9, o = i & 511;
        float s = 0.f;
        #pragma unroll
        for (int k = 0; k < Kn; k++) {
            float cs = 0.f;
            #pragma unroll
            for (int v = 0; v < Jn; v++) cs += adj[k*289 + v*17 + w];
            s += bg1[k * Cn + o] * cs;
        }
        g_b1m[i] = s;
        return;
    }
    i -= Jn * Cn;
    if (i < Jn * Cn) {                // b2m (+ b22)
        int w = i >> 9, o = i & 511;
        float s = b22[o];
        #pragma unroll
        for (int k = 0; k < Kn; k++) {
            float cs = 0.f;
            #pragma unroll
            for (int v = 0; v < Jn; v++) cs += adj[k*289 + v*17 + w];
            s += bg2[k * Cn + o] * cs;
        }
        g_b2m[i] = s;
        return;
    }
}

// ---------------- stage 1: LN(J) -> xa1(fp16) + xnh(fp16, k16) + xn16 --------
__global__ __launch_bounds__(256) void stage1_kernel(
    const float* __restrict__ x, const float* __restrict__ adj,
    const float* __restrict__ g1, const float* __restrict__ be1)
{
    __shared__ float sadjT[Kn * Jn * 18];
    __shared__ float sg1[Jn], sbe1[Jn];

    const int tid = threadIdx.x;
    const int b = blockIdx.x;

    for (int i = tid; i < Kn*Jn*Jn; i += 256) { int k = i/289, r = i%289, v = r/17, w = r%17; sadjT[(k*17+w)*18 + v] = adj[i]; }
    for (int i = tid; i < Kn*Jn; i += 256) sadjT[i*18 + 17] = 0.f;
    if (tid < Jn) { sg1[tid] = g1[tid]; sbe1[tid] = be1[tid]; }
    __syncthreads();

    const int c0 = tid, c1 = tid + 256;
    const float* xb = x + (size_t)b * (Jn*Cn);

    float xr0[Jn], xr1[Jn];
    #pragma unroll
    for (int j = 0; j < Jn; j++) { xr0[j] = xb[j*Cn + c0]; xr1[j] = xb[j*Cn + c1]; }

    float mu0 = 0.f, mu1 = 0.f;
    #pragma unroll
    for (int j = 0; j < Jn; j++) { mu0 += xr0[j]; mu1 += xr1[j]; }
    mu0 *= (1.0f/17.0f); mu1 *= (1.0f/17.0f);
    float v0 = 0.f, v1 = 0.f;
    #pragma unroll
    for (int j = 0; j < Jn; j++) { float d0 = xr0[j]-mu0, d1 = xr1[j]-mu1; v0 += d0*d0; v1 += d1*d1; }
    float rs0 = rsqrtf(v0*(1.0f/17.0f) + EPSF);
    float rs1 = rsqrtf(v1*(1.0f/17.0f) + EPSF);

    float xn0[18], xn1[18];
    #pragma unroll
    for (int j = 0; j < Jn; j++) {
        xn0[j] = (xr0[j]-mu0)*rs0*sg1[j] + sbe1[j];
        xn1[j] = (xr1[j]-mu1)*rs1*sg1[j] + sbe1[j];
    }
    xn0[17] = 0.f; xn1[17] = 0.f;

    // xa1 (fp16)
    #pragma unroll
    for (int k = 0; k < Kn; k++) {
        #pragma unroll
        for (int w = 0; w < Jn; w++) {
            const float2* ar = (const float2*)&sadjT[(k*17+w)*18];
            float s0 = 0.f, s1 = 0.f;
            #pragma unroll
            for (int p = 0; p < 9; p++) {
                float2 a = ar[p];
                s0 += a.x*xn0[2*p] + a.y*xn0[2*p+1];
                s1 += a.x*xn1[2*p] + a.y*xn1[2*p+1];
            }
            int idx = (b*17 + w)*KC + k*Cn;
            g_xah[idx + c0] = __float2half_rn(s0);
            g_xah[idx + c1] = __float2half_rn(s1);
        }
    }

    // xnh rows (b*512+c): 16 halves (j=0..15); element 16 separate
    {
        __half2 hx[8];
        #pragma unroll
        for (int p = 0; p < 8; p++) hx[p] = __floats2half2_rn(xn0[2*p], xn0[2*p+1]);
        uint4* d0 = (uint4*)(g_xnh + ((size_t)b*512 + c0) * 16);
        const uint4* s = (const uint4*)hx;
        d0[0] = s[0]; d0[1] = s[1];
        g_xn16[(size_t)b*512 + c0] = __float2half_rn(xn0[16]);

        #pragma unroll
        for (int p = 0; p < 8; p++) hx[p] = __floats2half2_rn(xn1[2*p], xn1[2*p+1]);
        uint4* d1 = (uint4*)(g_xnh + ((size_t)b*512 + c1) * 16);
        d1[0] = s[0]; d1[1] = s[1];
        g_xn16[(size_t)b*512 + c1] = __float2half_rn(xn1[16]);
    }
}

// ---------------- fused MLP1 on tensor cores (k=16 + rank-1) -----------------
// x2[b][j][c] = x[b][j][c] + (gelu(xn @ W11^T + b11) @ W12^T)[j] + b12[j]
// 128 rows (b,c) per CTA, 8 warps x 16 rows. GEMM1 d-frag == GEMM2 a-frag.
#define M1_XN   0            // [128][48B]   6144
#define M1_W11  6144         // [256][48B]   12288
#define M1_W12  18432        // [32][512B]   16384 (swizzled)
#define M1_X16  34816        // 128 floats
#define M1_WC16 35328        // 256 floats
#define M1_B11  36352        // 256 floats
#define M1_B12  37376        // 17 floats
#define M1_SMEM 37504

__global__ __launch_bounds__(256, 2) void mlp1_kernel(
    const float* __restrict__ x,
    const float* __restrict__ b11, const float* __restrict__ b12)
{
    extern __shared__ __align__(128) char sm[];
    uint32_t sbase;
    asm("{ .reg .u64 t; cvta.to.shared.u64 t, %1; cvt.u32.u64 %0, t; }" : "=r"(sbase) : "l"(sm));
    float* sx16  = (float*)(sm + M1_X16);
    float* swc16 = (float*)(sm + M1_WC16);
    float* sb11  = (float*)(sm + M1_B11);
    float* sb12  = (float*)(sm + M1_B12);

    const int tid = threadIdx.x, warp = tid >> 5, lane = tid & 31;
    const int rb = blockIdx.x * 128;

    // async loads
    {   // xnh tile: 128 rows x 32B, pitch 48
        const int r = tid >> 1, g = tid & 1;
        cpasync16(sbase + M1_XN + r*48 + g*16, g_xnh + ((size_t)(rb + r))*16 + g*8);
    }
    #pragma unroll
    for (int i = 0; i < 2; i++) {   // W11p: 256 rows x 32B, pitch 48
        int ci = tid + 256*i;
        int row = ci >> 1, g = ci & 1;
        cpasync16(sbase + M1_W11 + row*48 + g*16, g_W11h + row*16 + g*8);
    }
    #pragma unroll
    for (int i = 0; i < 4; i++) {   // W12p: 32 rows x 512B, swizzled
        int ci = tid + 256*i;
        int row = ci >> 5, g = ci & 31;
        int gp = (g & ~7) | ((g ^ row) & 7);
        cpasync16(sbase + M1_W12 + row*512 + gp*16, g_W12h + row*256 + g*8);
    }
    cp_commit();
    if (tid < 128) sx16[tid] = __half2float(g_xn16[rb + tid]);
    swc16[tid] = g_w11c16[tid];
    sb11[tid] = b11[tid];
    if (tid < Jn) sb12[tid] = b12[tid];
    cp_wait<0>();
    __syncthreads();

    const int quad = lane >> 3, qr = lane & 7;
    const int kq = quad >> 1, qh = quad & 1;
    const int g = lane >> 2, tg = lane & 3;

    // A-frag for GEMM1 (k=16, single k-step), persists
    uint32_t af[4];
    ldsm4(af, sbase + M1_XN + (warp*16 + qh*8 + qr)*48 + (kq << 4));
    const float xnr0 = sx16[warp*16 + g];
    const float xnr1 = sx16[warp*16 + g + 8];

    float oacc[3][4];
    #pragma unroll
    for (int n = 0; n < 3; n++)
        #pragma unroll
        for (int e = 0; e < 4; e++) oacc[n][e] = 0.f;

    #pragma unroll
    for (int q = 0; q < 4; q++) {
        float hacc[8][4];
        #pragma unroll
        for (int n = 0; n < 8; n++)
            #pragma unroll
            for (int e = 0; e < 4; e++) hacc[n][e] = 0.f;

        // GEMM1: hidden cols [64q, 64q+64), k=16
        #pragma unroll
        for (int nb = 0; nb < 4; nb++) {
            uint32_t bf[4];
            ldsm4(bf, sbase + M1_W11 + (q*64 + nb*16 + qh*8 + qr)*48 + (kq << 4));
            #pragma unroll
            for (int ni = 0; ni < 2; ni++) {
                uint32_t bb[2] = { bf[ni], bf[ni + 2] };
                mma_f16(hacc[nb*2 + ni], af, bb);
            }
        }

        // rank-1 (element 16) + bias + gelu + pack (d-frag -> a-frag)
        uint32_t h2[8][2];
        #pragma unroll
        for (int nt = 0; nt < 8; nt++) {
            int t0 = q*64 + nt*8 + tg*2;
            float w0 = swc16[t0], w1 = swc16[t0 + 1];
            float b0 = sb11[t0],  b1 = sb11[t0 + 1];
            float h00 = hacc[nt][0] + xnr0*w0 + b0;
            float h01 = hacc[nt][1] + xnr0*w1 + b1;
            float h10 = hacc[nt][2] + xnr1*w0 + b0;
            float h11 = hacc[nt][3] + xnr1*w1 + b1;
            h2[nt][0] = h2u(__floats2half2_rn(gelu_f(h00), gelu_f(h01)));
            h2[nt][1] = h2u(__floats2half2_rn(gelu_f(h10), gelu_f(h11)));
        }

        // GEMM2 partial: k-steps 4q..4q+3
        #pragma unroll
        for (int ksl = 0; ksl < 4; ksl++) {
            uint32_t a2[4] = { h2[2*ksl][0], h2[2*ksl][1], h2[2*ksl+1][0], h2[2*ksl+1][1] };
            int kgrp = (q*4 + ksl)*2 + kq;
            #pragma unroll
            for (int nb2 = 0; nb2 < 2; nb2++) {
                const int brow = nb2*16 + qh*8 + qr;
                int gp = (kgrp & ~7) | ((kgrp ^ brow) & 7);
                uint32_t bf[4];
                ldsm4(bf, sbase + M1_W12 + brow*512 + (gp << 4));
                #pragma unroll
                for (int ni = 0; ni < 2; ni++) {
                    int nt2 = nb2*2 + ni;
                    if (nt2 < 3) {
                        uint32_t bb[2] = { bf[ni], bf[ni + 2] };
                        mma_f16(oacc[nt2], a2, bb);
                    }
                }
            }
        }
    }

    // epilogue: x2 = x + mlp1 + b12 (rows (b,c), cols j)
    #pragma unroll
    for (int nt2 = 0; nt2 < 3; nt2++) {
        #pragma unroll
        for (int e = 0; e < 4; e++) {
            int j = nt2*8 + tg*2 + (e & 1);
            if (j < Jn) {
                int rowg = rb + warp*16 + g + ((e >> 1) * 8);
                int b = rowg >> 9, c = rowg & 511;
                size_t idx = ((size_t)b*17 + j)*512 + c;
                g_x2[idx] = x[idx] + oacc[nt2][e] + sb12[j];
            }
        }
    }
}

// ---------------- fused LN(C) + xa2 (one block per b) ------------------------
// phase 1: warp j normalizes row (b,j) -> xn2h + smem
// phase 2: thread c computes xa2 -> g_cat[:, 0:1536]
__global__ __launch_bounds__(544) void ln2xa2_kernel(
    const float* __restrict__ g2, const float* __restrict__ be2,
    const float* __restrict__ adj)
{
    __shared__ float sxn[Jn][Cn];
    __shared__ float sadjT[Kn * Jn * 18];

    const int tid = threadIdx.x;
    const int b = blockIdx.x;
    const int w = tid >> 5, lane = tid & 31;

    for (int i = tid; i < Kn*Jn*Jn; i += 544) { int k = i/289, r = i%289, v = r/17, ww = r%17; sadjT[(k*17+ww)*18 + v] = adj[i]; }
    for (int i = tid; i < Kn*Jn; i += 544) sadjT[i*18 + 17] = 0.f;

    {   // phase 1: LN over C for row (b, w), w = 0..16
        const int row = b*17 + w;
        const float4* xr = (const float4*)(g_x2 + (size_t)row * Cn);
        float4 a0 = xr[lane], a1 = xr[lane+32], a2 = xr[lane+64], a3 = xr[lane+96];
        float s = a0.x+a0.y+a0.z+a0.w + a1.x+a1.y+a1.z+a1.w
                + a2.x+a2.y+a2.z+a2.w + a3.x+a3.y+a3.z+a3.w;
        #pragma unroll
        for (int off = 16; off; off >>= 1) s += __shfl_xor_sync(0xffffffffu, s, off);
        float mu = s * (1.0f/512.0f);
        float q = 0.f;
        {
            float d;
            d=a0.x-mu; q+=d*d; d=a0.y-mu; q+=d*d; d=a0.z-mu; q+=d*d; d=a0.w-mu; q+=d*d;
            d=a1.x-mu; q+=d*d; d=a1.y-mu; q+=d*d; d=a1.z-mu; q+=d*d; d=a1.w-mu; q+=d*d;
            d=a2.x-mu; q+=d*d; d=a2.y-mu; q+=d*d; d=a2.z-mu; q+=d*d; d=a2.w-mu; q+=d*d;
            d=a3.x-mu; q+=d*d; d=a3.y-mu; q+=d*d; d=a3.z-mu; q+=d*d; d=a3.w-mu; q+=d*d;
        }
        #pragma unroll
        for (int off = 16; off; off >>= 1) q += __shfl_xor_sync(0xffffffffu, q, off);
        float rstd = rsqrtf(q * (1.0f/512.0f) + EPSF);

        const float4* gg = (const float4*)g2;
        const float4* bb = (const float4*)be2;
        __half2* oh = (__half2*)(g_xn2h + (size_t)row * Cn);
        #pragma unroll
        for (int i = 0; i < 4; i++) {
            float4 a = (i==0)?a0:(i==1)?a1:(i==2)?a2:a3;
            float4 gv = gg[lane + i*32], ev = bb[lane + i*32];
            float r0 = (a.x-mu)*rstd*gv.x + ev.x;
            float r1 = (a.y-mu)*rstd*gv.y + ev.y;
            float r2 = (a.z-mu)*rstd*gv.z + ev.z;
            float r3 = (a.w-mu)*rstd*gv.w + ev.w;
            int p = (lane + i*32) * 2;
            oh[p]   = __floats2half2_rn(r0, r1);
            oh[p+1] = __floats2half2_rn(r2, r3);
            int c = (lane + i*32) * 4;
            sxn[w][c+0] = r0; sxn[w][c+1] = r1; sxn[w][c+2] = r2; sxn[w][c+3] = r3;
        }
    }
    __syncthreads();

    if (tid < 512) {   // phase 2: xa2 for column c = tid
        const int c = tid;
        float xv[18];
        #pragma unroll
        for (int v = 0; v < Jn; v++) xv[v] = sxn[v][c];
        xv[17] = 0.f;
        #pragma unroll
        for (int k = 0; k < Kn; k++) {
            #pragma unroll
            for (int ww = 0; ww < Jn; ww++) {
                const float2* ar = (const float2*)&sadjT[(k*17+ww)*18];
                float s = 0.f;
                #pragma unroll
                for (int p = 0; p < 9; p++) { float2 a = ar[p]; s += a.x*xv[2*p] + a.y*xv[2*p+1]; }
                g_cat[(size_t)(b*17 + ww)*KCAT + k*Cn + c] = __float2half_rn(s);
            }
        }
    }
}

// ---------------- fp16 tensor-core GEMM, 128x128x32, 4-stage cp.async --------
// A: [M][Kd] half row-major. Bw: [N][Kd] half row-major. acc = A @ Bw^T (fp32).
// EPI 0: x2 += acc + b1m[(r%17)*512+c]                  (float out, stride 512)
// EPI 1: g_cat[r][1536+c] = half(gelu(acc + biasv[c]))  (half out, stride 3584)
// EPI 2: out = aux + acc + b2m[(r%17)*512+c]            (float out, stride 512)
#define NSTAGE 4
#define ABYTES 8192                      // 128 rows x 64 B
#define STAGE_BYTES (2*ABYTES)           // 16384
#define GEMM_SMEM (NSTAGE*STAGE_BYTES)   // 65536

template<int EPI>
__global__ __launch_bounds__(256, 2) void gemm_f16(
    const __half* __restrict__ A, const __half* __restrict__ Bw,
    void* __restrict__ outp, const float* __restrict__ biasv,
    const float* __restrict__ aux, int Kd)
{
    extern __shared__ __align__(128) char smem[];
    uint32_t sbase;
    asm("{ .reg .u64 t; cvta.to.shared.u64 t, %1; cvt.u32.u64 %0, t; }" : "=r"(sbase) : "l"(smem));

    const int tid  = threadIdx.x;
    const int warp = tid >> 5;
    const int lane = tid & 31;
    const int m0 = blockIdx.y * 128;
    const int n0 = blockIdx.x * 128;
    const int KT = Kd >> 5;

    const int lrow = tid >> 1;
    const int gsel = tid & 1;
    const int xw   = (lrow & 6) >> 1;
    const __half* gA = A  + (size_t)(m0 + lrow) * Kd + gsel * 16;
    const __half* gB = Bw + (size_t)(n0 + lrow) * Kd + gsel * 16;
    const uint32_t dA0 = sbase + lrow*64 + (((gsel*2 + 0) ^ xw) << 4);
    const uint32_t dA1 = sbase + lrow*64 + (((gsel*2 + 1) ^ xw) << 4);
    const uint32_t dB0 = dA0 + ABYTES;
    const uint32_t dB1 = dA1 + ABYTES;

    #pragma unroll
    for (int s = 0; s < NSTAGE - 1; s++) {
        const uint32_t so = s * STAGE_BYTES;
        cpasync16(dA0 + so, gA + s*32);
        cpasync16(dA1 + so, gA + s*32 + 8);
        cpasync16(dB0 + so, gB + s*32);
        cpasync16(dB1 + so, gB + s*32 + 8);
        cp_commit();
    }

    const int wm = warp >> 2, wn = warp & 3;
    const int quad = lane >> 3, qr = lane & 7;
    const int kq = quad >> 1;
    const int arow0 = wm*64 + (quad & 1)*8 + qr;
    const int brow0 = wn*32 + (quad & 1)*8 + qr;
    const int xwa = (arow0 & 6) >> 1;
    const int xwb = (brow0 & 6) >> 1;
    const uint32_t aAddr = sbase + arow0*64;
    const uint32_t bAddr = sbase + ABYTES + brow0*64;

    float acc[4][4][4];
    #pragma unroll
    for (int mi = 0; mi < 4; mi++)
        #pragma unroll
        for (int ni = 0; ni < 4; ni++)
            #pragma unroll
            for (int e = 0; e < 4; e++) acc[mi][ni][e] = 0.f;

    for (int it = 0; it < KT; it++) {
        if (it <= KT - 3)      cp_wait<2>();
        else if (it == KT - 2) cp_wait<1>();
        else                   cp_wait<0>();
        __syncthreads();

        if (it + NSTAGE - 1 < KT) {
            const uint32_t so = ((it + NSTAGE - 1) & (NSTAGE-1)) * STAGE_BYTES;
            const __half* ga = gA + (it + NSTAGE - 1)*32;
            const __half* gb = gB + (it + NSTAGE - 1)*32;
            cpasync16(dA0 + so, ga);
            cpasync16(dA1 + so, ga + 8);
            cpasync16(dB0 + so, gb);
            cpasync16(dB1 + so, gb + 8);
            cp_commit();
        }

        const uint32_t so = (it & (NSTAGE-1)) * STAGE_BYTES;
        #pragma unroll
        for (int ks = 0; ks < 2; ks++) {
            uint32_t af[4][4], bf[2][4];
            #pragma unroll
            for (int mi = 0; mi < 4; mi++)
                ldsm4(af[mi], aAddr + so + mi*1024 + (((ks*2 + kq) ^ xwa) << 4));
            #pragma unroll
            for (int nb = 0; nb < 2; nb++)
                ldsm4(bf[nb], bAddr + so + nb*1024 + (((ks*2 + kq) ^ xwb) << 4));
            #pragma unroll
            for (int mi = 0; mi < 4; mi++)
                #pragma unroll
                for (int ni = 0; ni < 4; ni++) {
                    uint32_t bb[2] = { bf[ni >> 1][ni & 1], bf[ni >> 1][(ni & 1) + 2] };
                    mma_f16(acc[mi][ni], af[mi], bb);
                }
        }
    }

    const int g = lane >> 2, tg = lane & 3;
    #pragma unroll
    for (int mi = 0; mi < 4; mi++) {
        const int rbm = m0 + wm*64 + mi*16 + g;
        #pragma unroll
        for (int half = 0; half < 2; half++) {
            const int r = rbm + half*8;
            #pragma unroll
            for (int ni = 0; ni < 4; ni++) {
                const int c = n0 + wn*32 + ni*8 + tg*2;
                const float v0 = acc[mi][ni][half*2 + 0];
                const float v1 = acc[mi][ni][half*2 + 1];
                if (EPI == 0) {
                    float* p = (float*)outp + (size_t)r * 512 + c;
                    const float* bb = biasv + (r % 17) * 512 + c;
                    float2 o = *(float2*)p;
                    o.x += v0 + bb[0]; o.y += v1 + bb[1];
                    *(float2*)p = o;
                } else if (EPI == 1) {
                    __half2* p = (__half2*)((__half*)outp + (size_t)r * KCAT + KC + c);
                    const float* bb = biasv + c;
                    *p = __floats2half2_rn(gelu_f(v0 + bb[0]), gelu_f(v1 + bb[1]));
                } else {
                    float* p = (float*)outp + (size_t)r * 512 + c;
                    const float* ax = aux + (size_t)r * 512 + c;
                    const float* bb = biasv + (r % 17) * 512 + c;
                    float2 a = *(const float2*)ax;
                    float2 o;
                    o.x = a.x + v0 + bb[0]; o.y = a.y + v1 + bb[1];
                    *(float2*)p = o;
                }
            }
        }
    }
}

// ---------------- launch ------------------------------------------------------
extern "C" void kernel_launch(void* const* d_in, const int* in_sizes, int n_in,
                              void* d_out, int out_size)
{
    const float* x   = (const float*)d_in[0];
    const float* adj = (const float*)d_in[1];
    const float* g1  = (const float*)d_in[2];
    const float* be1 = (const float*)d_in[3];
    const float* g2  = (const float*)d_in[4];
    const float* be2 = (const float*)d_in[5];
    const float* Wg1 = (const float*)d_in[6];
    const float* bg1 = (const float*)d_in[7];
    const float* Wg2 = (const float*)d_in[8];
    const float* bg2 = (const float*)d_in[9];
    const float* W11 = (const float*)d_in[10];
    const float* b11 = (const float*)d_in[11];
    const float* W12 = (const float*)d_in[12];
    const float* b12 = (const float*)d_in[13];
    const float* W21 = (const float*)d_in[14];
    const float* b21 = (const float*)d_in[15];
    const float* W22 = (const float*)d_in[16];
    const float* b22 = (const float*)d_in[17];
    float* out = (float*)d_out;

    __half *p_xah, *p_xn2h, *p_cat, *p_Wr1h, *p_Wcat, *p_W21h;
    float *p_x2, *p_b1m, *p_b2m;
    cudaGetSymbolAddress((void**)&p_xah,  g_xah);
    cudaGetSymbolAddress((void**)&p_x2,   g_x2);
    cudaGetSymbolAddress((void**)&p_xn2h, g_xn2h);
    cudaGetSymbolAddress((void**)&p_cat,  g_cat);
    cudaGetSymbolAddress((void**)&p_Wr1h, g_Wr1h);
    cudaGetSymbolAddress((void**)&p_Wcat, g_Wcat);
    cudaGetSymbolAddress((void**)&p_W21h, g_W21h);
    cudaGetSymbolAddress((void**)&p_b1m,  g_b1m);
    cudaGetSymbolAddress((void**)&p_b2m,  g_b2m);

    cudaFuncSetAttribute(gemm_f16<0>, cudaFuncAttributeMaxDynamicSharedMemorySize, GEMM_SMEM);
    cudaFuncSetAttribute(gemm_f16<1>, cudaFuncAttributeMaxDynamicSharedMemorySize, GEMM_SMEM);
    cudaFuncSetAttribute(gemm_f16<2>, cudaFuncAttributeMaxDynamicSharedMemorySize, GEMM_SMEM);
    cudaFuncSetAttribute(mlp1_kernel, cudaFuncAttributeMaxDynamicSharedMemorySize, M1_SMEM);

    // 1) weight prep
    {
        int total = Cn*KC + Cn*KCAT + CHn*Cn + TOKn*16 + TOKn + 32*TOKn + 2*(Jn*Cn);
        prep_kernel<<<(total + 255)/256, 256>>>(Wg1, Wg2, W21, W22, bg1, bg2, adj, W11, W12, b22);
    }
    // 2) stage1: LN(J) -> xa1 + xnh + xn16
    stage1_kernel<<<Bsz, 256>>>(x, adj, g1, be1);
    // 3) fused tensor MLP1: x2 = x + mlp1(xn) + b12
    mlp1_kernel<<<MR/128, 256, M1_SMEM>>>(x, b11, b12);
    // 4) GCN1: x2 += xa1 @ Wr1^T + b1m       (M=69632, K=1536, N=512)
    gemm_f16<0><<<dim3(Cn/128, M2/128), 256, GEMM_SMEM>>>(p_xah, p_Wr1h, p_x2, p_b1m, nullptr, KC);
    // 5) fused LN(C) + xa2 -> xn2h + g_cat[:, 0:1536]
    ln2xa2_kernel<<<Bsz, 544>>>(g2, be2, adj);
    // 6) MLP2 up: g_cat[:, 1536:] = half(gelu(xn2 @ W21^T + b21))  (K=512, N=2048)
    gemm_f16<1><<<dim3(CHn/128, M2/128), 256, GEMM_SMEM>>>(p_xn2h, p_W21h, p_cat, b21, nullptr, Cn);
    // 7) final fused GCN2+MLP2dn: out = x2 + cat @ Wcat^T + b2m'   (K=3584, N=512)
    gemm_f16<2><<<dim3(Cn/128, M2/128), 256, GEMM_SMEM>>>(p_cat, p_Wcat, out, p_b2m, p_x2, KCAT);
}